// round 12
// baseline (speedup 1.0000x reference)
#include <cuda_runtime.h>
#include <cstdint>
#include <math.h>

#define LSEQ 2304
#define DIMC 192
#define EC   384
#define NC   16
#define PC   64
#define HHC  6
#define KC   4
#define ROWS (KC*LSEQ)   /* 9216 */
#define ZXW  800         /* zx GEMM logical N: 384 z + 384 xh + 32 bc */
#define NSEG 8
#define TSEG (LSEQ/NSEG) /* 288 */

// ---------------- scratch (static device globals; no allocation) ----------------
static __device__ __align__(16) float g_xseq[ROWS*DIMC];      // tf32-rounded
static __device__ __align__(16) float g_projc[ROWS*EC];       // fp32 pre-silu (ssm half)
static __device__ __align__(16) float g_gsil [ROWS*EC];       // fp32 silu(gate half)
static __device__ __align__(16) float g_xssmt[ROWS*EC];       // tf32 silu(proj) (GEMM epi)
static __device__ __align__(16) float g_wcomb[EC*ZXW];        // tf32-rounded
static __device__ __align__(16) float g_winT[DIMC*768];       // tf32-rounded
static __device__ __align__(16) float g_wmoutT[EC*EC];        // tf32-rounded
static __device__ __align__(16) float g_woutT[EC*DIMC];       // tf32-rounded
static __device__ __align__(16) float g_z  [ROWS*EC];         // fp32 (zx epi split)
static __device__ __align__(16) float g_xh [ROWS*EC];         // fp32
static __device__ __align__(16) float g_bcb[ROWS*32];         // fp32
static __device__ __align__(16) float g_dtr[ROWS*HHC];
static __device__ __align__(16) float g_dtb[ROWS*HHC];        // 0.5*dt
static __device__ __align__(16) float g_rb[ROWS*HHC];
static __device__ __align__(16) float g_cum[ROWS*HHC];
static __device__ __align__(16) float g_Bt[ROWS*HHC*NC];
static __device__ __align__(16) float g_Ct[ROWS*HHC*NC];
static __device__ __align__(16) float g_y[ROWS*EC];
static __device__ __align__(16) float g_g[ROWS*EC];           // tf32-rounded
static __device__ __align__(16) float g_moG[ROWS*EC];         // mout * gsil (EPI 3)
static __device__ __align__(16) float g_mT[LSEQ*EC];          // tf32-rounded
static __device__ __align__(16) float g_pre[LSEQ*DIMC];
static __device__ __align__(16) float g_rc[KC*HHC*LSEQ];
static __device__ __align__(16) float g_hend[KC*HHC*NSEG*PC*NC];
static __device__ __align__(16) float g_hin[KC*HHC*NSEG*PC*NC];

__device__ __forceinline__ float siluf(float v){
    return __fdividef(v, 1.f + __expf(-v));
}
__device__ __forceinline__ float f2tf32f(float f){
    uint32_t u; asm("cvt.rna.tf32.f32 %0, %1;" : "=r"(u) : "f"(f));
    return __uint_as_float(u);
}
__device__ __forceinline__ void ldsm_x4(uint32_t &r0, uint32_t &r1, uint32_t &r2, uint32_t &r3,
                                        uint32_t addr){
    asm volatile("ldmatrix.sync.aligned.m8n8.x4.shared.b16 {%0,%1,%2,%3}, [%4];"
                 : "=r"(r0), "=r"(r1), "=r"(r2), "=r"(r3) : "r"(addr));
}

#define CP16(dst,src) asm volatile("cp.async.cg.shared.global [%0],[%1],16;\n"::"r"(dst),"l"(src))
#define CP16Z(dst,src) asm volatile("cp.async.cg.shared.global [%0],[%1],16,0;\n"::"r"(dst),"l"(src))
#define CP4(dst,src)  asm volatile("cp.async.ca.shared.global [%0],[%1],4;\n"::"r"(dst),"l"(src))
#define CPCOMMIT()    asm volatile("cp.async.commit_group;\n")
#define CPWAIT1()     asm volatile("cp.async.wait_group 1;\n")

// ---------------- fused prep: build 4-dir sequence + tf32 weight copies ----------------
#define WP1 (DIMC*768)
#define WP2 (WP1 + EC*EC)
#define WP3 (WP2 + EC*DIMC)
#define WP4 (WP3 + EC*ZXW)
#define PREP_BUILD_BLKS (DIMC*KC)   /* 768 */
#define PREP_W_BLKS ((WP4+255)/256)
__global__ __launch_bounds__(256) void k_prep(const float* __restrict__ x, float* __restrict__ xseq,
                        const float* __restrict__ w_in, const float* __restrict__ w_mout,
                        const float* __restrict__ w_out, const float* __restrict__ wzx,
                        const float* __restrict__ wbc,
                        float* __restrict__ winT, float* __restrict__ wmoutT,
                        float* __restrict__ woutT, float* __restrict__ wcomb){
    int tid = threadIdx.x;
    if (blockIdx.x < PREP_BUILD_BLKS){
        __shared__ float sm[LSEQ + LSEQ/48];
        int d = blockIdx.x >> 2;
        int k = blockIdx.x & 3;
        for (int i = tid; i < LSEQ; i += 256)
            sm[i + i/48] = x[d*LSEQ + i];
        __syncthreads();
        size_t obase = (size_t)k*(LSEQ*DIMC) + (size_t)d*LSEQ;
        for (int l = tid; l < LSEQ; l += 256){
            int m;
            if      (k==0) m = l;
            else if (k==1) m = (l%48)*48 + l/48;
            else if (k==2) m = 2303 - l;
            else { int lr = 2303-l; m = (lr%48)*48 + lr/48; }
            xseq[obase + l] = f2tf32f(sm[m + m/48]);
        }
        return;
    }
    int idx = (blockIdx.x - PREP_BUILD_BLKS)*256 + tid;
    if (idx >= WP4) return;
    if (idx < WP1){ winT[idx] = f2tf32f(w_in[idx]); return; }
    if (idx < WP2){ int i = idx-WP1; wmoutT[i] = f2tf32f(w_mout[i]); return; }
    if (idx < WP3){ int i = idx-WP2; woutT[i] = f2tf32f(w_out[i]); return; }
    int i = idx-WP3;
    int kk = i / ZXW, j = i % ZXW;
    float v = (j < 768) ? wzx[kk*768 + j] : wbc[kk*32 + (j-768)];
    wcomb[i] = f2tf32f(v);
}

// ---------------- tf32 tensor-core GEMM, BK=32, 3-stage cp.async, 1 sync/k-tile ----------------
// BM=128, BN=128. 8 warps: 2(m) x 4(n), warp tile 64x32, mma m16n8k8, A via ldmatrix.
// (R10 inner-loop form: measured best.)
#define GEMM_SMEM ((3*128*36 + 3*32*136)*4)
#define AS(b,r,c) Asp[(b)*128*36 + (r)*36 + (c)]
#define BS(b,r,c) Bsp[(b)*32*136 + (r)*136 + (c)]
template<int EPI>
__global__ __launch_bounds__(256,2) void k_gemm(const float* __restrict__ A,
                                                const float* __restrict__ B,
                                                float* __restrict__ C,
                                                int M, int N, int LDA, int KLEN,
                                                float* __restrict__ o1,
                                                float* __restrict__ o2,
                                                float* __restrict__ o3){
    extern __shared__ float dynsmem[];
    float* Asp = dynsmem;
    float* Bsp = dynsmem + 3*128*36;
    const int BM=128, BN=128, BK=32;
    int tid  = threadIdx.x;
    int warp = tid>>5, lane = tid&31;
    int wm = warp>>2, wn = warp&3;
    int gid = lane>>2, tig = lane&3;
    int bm = blockIdx.y*BM, bn = blockIdx.x*BN;

    int q = lane>>3, rl = lane&7;
    uint32_t aAddrBase = (uint32_t)__cvta_generic_to_shared(Asp)
        + (uint32_t)((((q&1)*8 + rl)*36 + (q>>1)*4) * 4)
        + (uint32_t)(wm*64*36*4);

    float acc[4][4][4];
    #pragma unroll
    for (int m=0;m<4;m++)
        #pragma unroll
        for (int n=0;n<4;n++)
            #pragma unroll
            for (int i=0;i<4;i++) acc[m][n][i]=0.f;

    auto stage = [&](int buf, int k0){
        #pragma unroll
        for (int j=0;j<4;j++){
            int i = tid + j*256;          // A: 128x32 = 1024 float4
            int r = i>>3, kc = i&7;
            uint32_t dst = (uint32_t)__cvta_generic_to_shared(&AS(buf, r, kc*4));
            CP16(dst, &A[(size_t)(bm+r)*LDA + k0 + kc*4]);
        }
        #pragma unroll
        for (int j=0;j<4;j++){
            int i = tid + j*256;          // B: 32x128 = 1024 float4
            int r = i>>5, c = i&31;
            uint32_t dst = (uint32_t)__cvta_generic_to_shared(&BS(buf, r, c*4));
            if (bn + c*4 + 4 <= N) CP16(dst, &B[(size_t)(k0+r)*N + bn + c*4]);
            else                   CP16Z(dst, B);
        }
        CPCOMMIT();
    };

    int nk = KLEN/BK;      // >= 6 for all calls
    stage(0, 0);
    stage(1, BK);
    for (int kt=0; kt<nk; ++kt){
        CPWAIT1();                     // group kt complete (kt+1 may be pending)
        __syncthreads();               // all warps done with buf[(kt-1)%3]
        if (kt+2 < nk) stage((kt+2)%3, (kt+2)*BK);   // overwrites buf[(kt-1)%3] - safe
        else CPCOMMIT();
        int buf = kt - (kt/3)*3;

        uint32_t aBufBase = aAddrBase + (uint32_t)(buf*128*36*4);
        #pragma unroll
        for (int kk=0; kk<4; kk++){
            int kb = kk*8;
            uint32_t a[4][4];
            #pragma unroll
            for (int m=0;m<4;m++){
                ldsm_x4(a[m][0], a[m][1], a[m][2], a[m][3],
                        aBufBase + (uint32_t)((m*16*36 + kb)*4));
            }
            uint32_t b[4][2];
            #pragma unroll
            for (int n=0;n<4;n++){
                int nc = wn*32 + n*8;
                b[n][0] = __float_as_uint(BS(buf, kb+tig,   nc+gid));
                b[n][1] = __float_as_uint(BS(buf, kb+tig+4, nc+gid));
            }
            #pragma unroll
            for (int m=0;m<4;m++)
                #pragma unroll
                for (int n=0;n<4;n++){
                    asm volatile(
                        "mma.sync.aligned.m16n8k8.row.col.f32.tf32.tf32.f32 "
                        "{%0,%1,%2,%3}, {%4,%5,%6,%7}, {%8,%9}, {%0,%1,%2,%3};"
                        : "+f"(acc[m][n][0]), "+f"(acc[m][n][1]),
                          "+f"(acc[m][n][2]), "+f"(acc[m][n][3])
                        : "r"(a[m][0]), "r"(a[m][1]), "r"(a[m][2]), "r"(a[m][3]),
                          "r"(b[n][0]), "r"(b[n][1]));
                }
        }
    }
    #pragma unroll
    for (int m=0;m<4;m++){
        int row0 = bm + wm*64 + m*16 + gid;
        #pragma unroll
        for (int n=0;n<4;n++){
            int col = bn + wn*32 + n*8 + tig*2;
            #pragma unroll
            for (int cc=0; cc<2; cc++){
                int cl = col + cc;
                if (cl >= N) continue;
                float v0 = acc[m][n][cc];       // row0
                float v1 = acc[m][n][2+cc];     // row0+8
                if (EPI == 0){
                    C[(size_t)row0*N + cl] = v0;
                    C[(size_t)(row0+8)*N + cl] = v1;
                } else if (EPI == 1){
                    if (cl < 384){
                        C[(size_t)row0*EC + cl] = v0;          // compact pre-silu fp32
                        C[(size_t)(row0+8)*EC + cl] = v1;
                        o1[(size_t)row0*EC + cl] = f2tf32f(siluf(v0));
                        o1[(size_t)(row0+8)*EC + cl] = f2tf32f(siluf(v1));
                    } else {
                        o2[(size_t)row0*EC + cl-384] = siluf(v0);  // gate silu fp32
                        o2[(size_t)(row0+8)*EC + cl-384] = siluf(v1);
                    }
                } else if (EPI == 2){  // split z / xh / bc
                    if (cl < 384){
                        o1[(size_t)row0*EC + cl] = v0;
                        o1[(size_t)(row0+8)*EC + cl] = v1;
                    } else if (cl < 768){
                        o2[(size_t)row0*EC + cl-384] = v0;
                        o2[(size_t)(row0+8)*EC + cl-384] = v1;
                    } else {
                        o3[(size_t)row0*32 + cl-768] = v0;
                        o3[(size_t)(row0+8)*32 + cl-768] = v1;
                    }
                } else {  // EPI == 3: C = acc * o1 (gate silu)
                    C[(size_t)row0*N + cl] = v0 * o1[(size_t)row0*EC + cl];
                    C[(size_t)(row0+8)*N + cl] = v1 * o1[(size_t)(row0+8)*EC + cl];
                }
            }
        }
    }
}

// ---------------- dt GEMV: dtr[row][h] = silu(projc[row,:])·w_dt[:,h] (fp32) ----------------
__global__ __launch_bounds__(256) void k_dtgemv(const float* __restrict__ projc,
                                                const float* __restrict__ w_dt,
                                                float* __restrict__ dtr){
    __shared__ float wst[HHC*EC];   // transposed [h][e] -> bank = lane, conflict-free
    int tid = threadIdx.x;
    for (int i=tid; i<EC*HHC; i+=256){
        int h = i % HHC, e = i / HHC;
        wst[h*EC + e] = w_dt[i];
    }
    __syncthreads();
    int warp = tid>>5, lane = tid&31;
    int row = blockIdx.x*8 + warp;
    float s[HHC];
    #pragma unroll
    for (int h=0;h<HHC;h++) s[h]=0.f;
    #pragma unroll
    for (int j=0;j<12;j++){
        int e = lane + j*32;
        float xv = siluf(projc[(size_t)row*EC + e]);
        #pragma unroll
        for (int h=0;h<HHC;h++) s[h] = fmaf(xv, wst[h*EC+e], s[h]);
    }
    #pragma unroll
    for (int h=0;h<HHC;h++){
        #pragma unroll
        for (int off=16; off>=1; off>>=1) s[h] += __shfl_xor_sync(0xffffffffu, s[h], off);
    }
    #pragma unroll
    for (int h=0;h<HHC;h++)
        if (lane == h) dtr[(size_t)row*HHC + h] = s[h];
}

// ---------------- dt path: softplus, r, cumsum (precise exp) ----------------
__global__ void k_dtscan(const float* __restrict__ dtr, const float* __restrict__ dt_bias,
                         const float* __restrict__ A_log,
                         float* __restrict__ dtb, float* __restrict__ rb, float* __restrict__ cumb){
    int k = blockIdx.x / HHC, h = blockIdx.x % HHC;
    __shared__ float part[256];
    float expA = expf(A_log[h]);
    float bias = dt_bias[h];
    int tid = threadIdx.x;
    int tbase = tid*9;
    float loc[9]; float s = 0.f;
    #pragma unroll
    for (int i=0;i<9;i++){
        size_t row = (size_t)k*LSEQ + tbase + i;
        float v  = dtr[row*HHC + h] + bias;
        float dt = (v > 20.f) ? v : log1pf(expf(v));
        dtb[row*HHC+h] = 0.5f*dt;
        rb [row*HHC+h] = expf(-dt*expA);
        s += dt; loc[i] = s;
    }
    part[tid] = s; __syncthreads();
    for (int off=1; off<256; off<<=1){
        float add = (tid >= off) ? part[tid-off] : 0.f;
        __syncthreads();
        part[tid] += add;
        __syncthreads();
    }
    float offset = part[tid] - s;
    #pragma unroll
    for (int i=0;i<9;i++){
        size_t row = (size_t)k*LSEQ + tbase + i;
        cumb[row*HHC+h] = loc[i] + offset;
    }
}

// ---------------- rms(B/C) + rotary: warp per row, deduplicated sincos ----------------
// Only 48 unique (h,i) angle pairs per row; lane l computes pairs l and l+32
// (2 sincosf/thread vs 6), consumers fetch via shfl. Same precise sincosf.
__global__ __launch_bounds__(256) void k_rot(const float* __restrict__ bcb, const float* __restrict__ bias_bc,
                                             const float* __restrict__ theta, const float* __restrict__ cumb,
                                             float* __restrict__ Bt, float* __restrict__ Ct){
    int row  = (blockIdx.x*blockDim.x + threadIdx.x) >> 5;
    int lane = threadIdx.x & 31;
    if (row >= ROWS) return;
    // rms over B (lanes 0-15) and C (lanes 16-31) halves
    float bc = bcb[(size_t)row*32 + lane] + bias_bc[lane];
    float s = bc*bc;
    s += __shfl_xor_sync(0xffffffffu, s, 1);
    s += __shfl_xor_sync(0xffffffffu, s, 2);
    s += __shfl_xor_sync(0xffffffffu, s, 4);
    s += __shfl_xor_sync(0xffffffffu, s, 8);
    float rn = rsqrtf(s*(1.f/16.f) + 1e-6f);
    float v = bc * rn;

    // cumb row staged across lanes 0-5
    float cval = (lane < HHC) ? cumb[(size_t)row*HHC + lane] : 0.f;
    // pair0 = lane (h = lane>>3, i = lane&7); pair1 = lane+32 (valid for lane<16)
    float th0 = theta[lane];
    float th1 = (lane < 16) ? theta[32 + lane] : 0.f;
    float cd0 = __shfl_sync(0xffffffffu, cval, lane>>3);
    float cd1 = __shfl_sync(0xffffffffu, cval, 4 + (lane>>3));   // h=4,5 for lane<16
    float s0, c0, s1, c1;
    sincosf(cd0*th0, &s0, &c0);
    sincosf(cd1*th1, &s1, &c1);

    int j = lane & 15;
    int half = lane & 16;
    int i = j >> 1;
    float v0 = __shfl_sync(0xffffffffu, v, half + 2*i);
    float v1 = __shfl_sync(0xffffffffu, v, half + 2*i + 1);
    bool odd = (j & 1) != 0;
    #pragma unroll
    for (int h=0; h<HHC; h++){
        int p = h*8 + i;
        float cc = (h < 4) ? __shfl_sync(0xffffffffu, c0, p)
                           : __shfl_sync(0xffffffffu, c1, p - 32);
        float ss = (h < 4) ? __shfl_sync(0xffffffffu, s0, p)
                           : __shfl_sync(0xffffffffu, s1, p - 32);
        float o = odd ? fmaf(-v0, ss, v1*cc) : fmaf(v0, cc, v1*ss);
        float* dst = half ? Ct : Bt;
        dst[((size_t)row*HHC + h)*16 + j] = o;
    }
}

// ---------------- scan phase A: per-segment local scan (h_in = 0) ----------------
#define SCH 32
__global__ __launch_bounds__(256) void k_scanA(const float* __restrict__ Bt, const float* __restrict__ Ct,
                                               const float* __restrict__ xh, const float* __restrict__ dtb,
                                               const float* __restrict__ rb, const float* __restrict__ Dsk,
                                               float* __restrict__ y, float* __restrict__ rc,
                                               float* __restrict__ hend){
    __shared__ __align__(16) float Bs[2][SCH][16];
    __shared__ __align__(16) float Cs[2][SCH][16];
    __shared__ __align__(16) float Xs[2][SCH][64];
    __shared__ float Ds[2][SCH];
    __shared__ float Rs[2][SCH];
    __shared__ __align__(16) float Ys[SCH][64];
    __shared__ float Rys[SCH];

    int kh = blockIdx.x; int k = kh/HHC, h = kh%HHC;
    int seg = blockIdx.y;
    int tseg0 = seg*TSEG;
    int tid = threadIdx.x;
    int p = tid>>2, ng = tid&3;
    size_t bBase = ((size_t)k*LSEQ*HHC + h)*16;
    size_t xBase = (size_t)k*LSEQ*EC + (size_t)h*64;
    size_t sBase = (size_t)k*LSEQ*HHC + h;
    float dsk = Dsk[h];
    float* ybase = y + (size_t)k*LSEQ*EC + h*64;
    size_t rcBase = (size_t)kh*LSEQ;

    auto stage = [&](int buf, int t0){
        {
            int id = tid & 127;
            int tl = id>>2, sg = id&3;
            size_t off = bBase + (size_t)(t0+tl)*96 + sg*4;
            if (tid < 128){
                uint32_t d = (uint32_t)__cvta_generic_to_shared(&Bs[buf][tl][sg*4]);
                CP16(d, &Bt[off]);
            } else {
                uint32_t d = (uint32_t)__cvta_generic_to_shared(&Cs[buf][tl][sg*4]);
                CP16(d, &Ct[off]);
            }
        }
        #pragma unroll
        for (int j=0;j<2;j++){
            int i = tid + j*256;
            int tl = i>>4, c = i&15;
            uint32_t d = (uint32_t)__cvta_generic_to_shared(&Xs[buf][tl][c*4]);
            CP16(d, &xh[xBase + (size_t)(t0+tl)*EC + c*4]);
        }
        if (tid < SCH){
            uint32_t d = (uint32_t)__cvta_generic_to_shared(&Ds[buf][tid]);
            CP4(d, &dtb[sBase + (size_t)(t0+tid)*HHC]);
        } else if (tid < 2*SCH){
            int tl = tid - SCH;
            uint32_t d = (uint32_t)__cvta_generic_to_shared(&Rs[buf][tl]);
            CP4(d, &rb[sBase + (size_t)(t0+tl)*HHC]);
        }
        CPCOMMIT();
    };

    float hs0=0.f,hs1=0.f,hs2=0.f,hs3=0.f;
    float bx0=0.f,bx1=0.f,bx2=0.f,bx3=0.f;
    if (seg > 0){
        int tp = tseg0 - 1;
        float4 Bp = *(const float4*)&Bt[bBase + (size_t)tp*96 + ng*4];
        float xp = xh[xBase + (size_t)tp*EC + p];
        bx0 = Bp.x*xp; bx1 = Bp.y*xp; bx2 = Bp.z*xp; bx3 = Bp.w*xp;
    }
    float rp = 1.f;

    stage(0, tseg0);
    const int NCHUNK = TSEG/SCH;   // 9
    for (int c=0; c<NCHUNK; ++c){
        int buf = c&1;
        if (c+1 < NCHUNK) stage(buf^1, tseg0 + (c+1)*SCH);
        else CPCOMMIT();
        CPWAIT1();
        __syncthreads();

        #pragma unroll 4
        for (int t=0; t<SCH; ++t){
            float4 Bv = *(const float4*)&Bs[buf][t][ng*4];
            float4 Cv = *(const float4*)&Cs[buf][t][ng*4];
            float xv = Xs[buf][t][p];
            float ad = Ds[buf][t];
            float rv = Rs[buf][t];
            float G0 = Bv.x*xv, G1 = Bv.y*xv, G2 = Bv.z*xv, G3 = Bv.w*xv;
            float u0 = fmaf(rv,bx0,G0), u1 = fmaf(rv,bx1,G1);
            float u2 = fmaf(rv,bx2,G2), u3 = fmaf(rv,bx3,G3);
            hs0 = fmaf(rv,hs0,ad*u0); hs1 = fmaf(rv,hs1,ad*u1);
            hs2 = fmaf(rv,hs2,ad*u2); hs3 = fmaf(rv,hs3,ad*u3);
            bx0=G0; bx1=G1; bx2=G2; bx3=G3;
            rp *= rv;
            float v = fmaf(Cv.x,hs0, fmaf(Cv.y,hs1, fmaf(Cv.z,hs2, Cv.w*hs3)));
            v += __shfl_xor_sync(0xffffffffu, v, 1);
            v += __shfl_xor_sync(0xffffffffu, v, 2);
            if (ng == 0) Ys[t][p] = fmaf(dsk, xv, v);
            if (tid == 0) Rys[t] = rp;
        }
        __syncthreads();
        int t0 = tseg0 + c*SCH;
        #pragma unroll
        for (int j=0;j<2;j++){
            int i = tid + j*256;
            int tl = i>>4, cc = i&15;
            *(float4*)&ybase[(size_t)(t0+tl)*EC + cc*4] = *(const float4*)&Ys[tl][cc*4];
        }
        if (tid < SCH) rc[rcBase + t0 + tid] = Rys[tid];
    }
    float4 he = make_float4(hs0,hs1,hs2,hs3);
    *(float4*)&hend[(((size_t)kh*NSEG + seg)*PC + p)*NC + ng*4] = he;
}

// ---------------- scan phase B: sequential combine of segment boundary states ----------------
__global__ __launch_bounds__(256) void k_scanB(const float* __restrict__ hend,
                                               const float* __restrict__ rc,
                                               float* __restrict__ hin){
    int kh = blockIdx.x;
    int tid = threadIdx.x;
    int p = tid>>2, ng = tid&3;
    float4 hi = make_float4(0.f,0.f,0.f,0.f);
    #pragma unroll
    for (int s=0; s<NSEG; ++s){
        size_t idx = (((size_t)kh*NSEG + s)*PC + p)*NC + ng*4;
        *(float4*)&hin[idx] = hi;
        float4 he = *(const float4*)&hend[idx];
        float Rseg = rc[(size_t)kh*LSEQ + s*TSEG + TSEG-1];
        hi.x = fmaf(Rseg, hi.x, he.x);
        hi.y = fmaf(Rseg, hi.y, he.y);
        hi.z = fmaf(Rseg, hi.z, he.z);
        hi.w = fmaf(Rseg, hi.w, he.w);
    }
}

// ---------------- scan phase C: fixup y += R(t) * (C_t · h_in) ----------------
__global__ __launch_bounds__(256) void k_scanC(const float* __restrict__ Ct,
                                               const float* __restrict__ rc,
                                               const float* __restrict__ hin,
                                               float* __restrict__ y){
    int seg = blockIdx.y;
    if (seg == 0) return;
    __shared__ float Hs[PC][NC+1];
    __shared__ float Cs[SCH][NC+1];
    __shared__ float Rsh[SCH];
    int kh = blockIdx.x; int k = kh/HHC, h = kh%HHC;
    int tid = threadIdx.x;
    int p = tid&63, tq = tid>>6;
    size_t hBase = ((size_t)kh*NSEG + seg)*PC*NC;
    for (int i=tid; i<PC*NC; i+=256) Hs[i>>4][i&15] = hin[hBase + i];
    __syncthreads();
    float hn[NC];
    #pragma unroll
    for (int i=0;i<NC;i++) hn[i] = Hs[p][i];

    size_t bBase = ((size_t)k*LSEQ*HHC + h)*16;
    size_t rcBase = (size_t)kh*LSEQ;
    float* ybase = y + (size_t)k*LSEQ*EC + h*64;
    int tseg0 = seg*TSEG;

    for (int c=0; c<TSEG/SCH; ++c){
        int t0 = tseg0 + c*SCH;
        for (int i=tid; i<SCH*NC; i+=256){
            int tl = i>>4, nn = i&15;
            Cs[tl][nn] = Ct[bBase + (size_t)(t0+tl)*96 + nn];
        }
        if (tid < SCH) Rsh[tid] = rc[rcBase + t0 + tid];
        __syncthreads();
        if (Rsh[0] == 0.f) break;
        #pragma unroll
        for (int jt=0; jt<SCH/4; ++jt){
            int tl = tq + jt*4;
            float R = Rsh[tl];
            if (R != 0.f){
                float corr = 0.f;
                #pragma unroll
                for (int i=0;i<NC;i++) corr = fmaf(Cs[tl][i], hn[i], corr);
                ybase[(size_t)(t0+tl)*EC + p] += R*corr;
            }
        }
        __syncthreads();
    }
}

// ---------------- g = tf32(rms(y * silu(z)) * rms_w)  (warp per row, compact z) ----------------
__global__ void k_gate(const float* __restrict__ y, const float* __restrict__ z,
                       const float* __restrict__ rms_w, float* __restrict__ g){
    int warp = (blockIdx.x*blockDim.x + threadIdx.x) >> 5;
    int lane = threadIdx.x & 31;
    if (warp >= ROWS) return;
    size_t base = (size_t)warp*EC;
    float v[12]; float s2 = 0.f;
    #pragma unroll
    for (int j=0;j<12;j++){
        int e = lane + j*32;
        float t = y[base + e] * siluf(z[base + e]);
        v[j] = t; s2 += t*t;
    }
    #pragma unroll
    for (int off=16; off>=1; off>>=1) s2 += __shfl_xor_sync(0xffffffffu, s2, off);
    float rn = rsqrtf(s2*(1.f/384.f) + 1e-6f);
    #pragma unroll
    for (int j=0;j<12;j++){
        int e = lane + j*32;
        g[base + e] = f2tf32f(v[j]*rn*rms_w[e]);
    }
}

// ---------------- merge 4 dirs of moG -> mT (tf32) ----------------
__global__ void k_xmerge(const float* __restrict__ moG, float* __restrict__ mT){
    int idx = blockIdx.x*blockDim.x + threadIdx.x;
    if (idx >= LSEQ*EC) return;
    int l = idx / EC, e = idx % EC;
    int lt = (l%48)*48 + l/48;
    size_t r0 = (size_t)l*EC + e;
    size_t r1 = (size_t)(LSEQ + lt)*EC + e;
    size_t r2 = (size_t)(2*LSEQ + 2303 - l)*EC + e;
    size_t r3 = (size_t)(3*LSEQ + 2303 - lt)*EC + e;
    mT[idx] = f2tf32f(moG[r0] + moG[r1] + moG[r2] + moG[r3]);
}

// ---------------- LayerNorm + residual ----------------
__global__ void k_ln(const float* __restrict__ pre, const float* __restrict__ x,
                     const float* __restrict__ ln_g, const float* __restrict__ ln_b,
                     const float* __restrict__ res_scale, float* __restrict__ out){
    int warp = (blockIdx.x*blockDim.x + threadIdx.x) >> 5;
    int lane = threadIdx.x & 31;
    if (warp >= LSEQ) return;
    int l = warp;
    float v[6]; float s = 0.f;
    #pragma unroll
    for (int j=0;j<6;j++){ v[j] = pre[(size_t)l*DIMC + lane + j*32]; s += v[j]; }
    #pragma unroll
    for (int off=16; off>=1; off>>=1) s += __shfl_xor_sync(0xffffffffu, s, off);
    float mu = s*(1.f/192.f);
    float q = 0.f;
    #pragma unroll
    for (int j=0;j<6;j++){ float d = v[j]-mu; q += d*d; }
    #pragma unroll
    for (int off=16; off>=1; off>>=1) q += __shfl_xor_sync(0xffffffffu, q, off);
    float inv = rsqrtf(q*(1.f/192.f) + 1e-5f);
    float rs = res_scale[0];
    #pragma unroll
    for (int j=0;j<6;j++){
        int d = lane + j*32;
        out[(size_t)d*LSEQ + l] = x[(size_t)d*LSEQ + l]
            + rs*((v[j]-mu)*inv*ln_g[d] + ln_b[d]);
    }
}

// ---------------- launch ----------------
extern "C" void kernel_launch(void* const* d_in, const int* in_sizes, int n_in,
                              void* d_out, int out_size){
    (void)in_sizes; (void)n_in; (void)out_size;
    const float* x        = (const float*)d_in[0];
    const float* w_in     = (const float*)d_in[1];
    const float* w_zx     = (const float*)d_in[2];
    const float* w_bc     = (const float*)d_in[3];
    const float* bias_bc  = (const float*)d_in[4];
    const float* w_dt     = (const float*)d_in[5];
    const float* dt_bias  = (const float*)d_in[6];
    const float* A_log    = (const float*)d_in[7];
    const float* theta    = (const float*)d_in[8];
    const float* D_skip   = (const float*)d_in[9];
    const float* rms_w    = (const float*)d_in[10];
    const float* w_mout   = (const float*)d_in[11];
    const float* w_out    = (const float*)d_in[12];
    const float* ln_g     = (const float*)d_in[13];
    const float* ln_b     = (const float*)d_in[14];
    const float* resscale = (const float*)d_in[15];
    float* out = (float*)d_out;

    float *b_xseq,*b_projc,*b_gsil,*b_xssmt,*b_wcomb,*b_winT,*b_wmoutT,*b_woutT;
    float *b_z,*b_xh,*b_bcb,*b_dtr,*b_dtb,*b_rb,*b_cum,*b_Bt,*b_Ct,*b_y,*b_g,*b_moG,*b_mT,*b_pre;
    float *b_rc,*b_hend,*b_hin;
    cudaGetSymbolAddress((void**)&b_xseq,  g_xseq);
    cudaGetSymbolAddress((void**)&b_projc, g_projc);
    cudaGetSymbolAddress((void**)&b_gsil,  g_gsil);
    cudaGetSymbolAddress((void**)&b_xssmt, g_xssmt);
    cudaGetSymbolAddress((void**)&b_wcomb, g_wcomb);
    cudaGetSymbolAddress((void**)&b_winT,  g_winT);
    cudaGetSymbolAddress((void**)&b_wmoutT,g_wmoutT);
    cudaGetSymbolAddress((void**)&b_woutT, g_woutT);
    cudaGetSymbolAddress((void**)&b_z,     g_z);
    cudaGetSymbolAddress((void**)&b_xh,    g_xh);
    cudaGetSymbolAddress((void**)&b_bcb,   g_bcb);
    cudaGetSymbolAddress((void**)&b_dtr,   g_dtr);
    cudaGetSymbolAddress((void**)&b_dtb,   g_dtb);
    cudaGetSymbolAddress((void**)&b_rb,    g_rb);
    cudaGetSymbolAddress((void**)&b_cum,   g_cum);
    cudaGetSymbolAddress((void**)&b_Bt,    g_Bt);
    cudaGetSymbolAddress((void**)&b_Ct,    g_Ct);
    cudaGetSymbolAddress((void**)&b_y,     g_y);
    cudaGetSymbolAddress((void**)&b_g,     g_g);
    cudaGetSymbolAddress((void**)&b_moG,   g_moG);
    cudaGetSymbolAddress((void**)&b_mT,    g_mT);
    cudaGetSymbolAddress((void**)&b_pre,   g_pre);
    cudaGetSymbolAddress((void**)&b_rc,    g_rc);
    cudaGetSymbolAddress((void**)&b_hend,  g_hend);
    cudaGetSymbolAddress((void**)&b_hin,   g_hin);

    cudaFuncSetAttribute(k_gemm<0>, cudaFuncAttributeMaxDynamicSharedMemorySize, GEMM_SMEM);
    cudaFuncSetAttribute(k_gemm<1>, cudaFuncAttributeMaxDynamicSharedMemorySize, GEMM_SMEM);
    cudaFuncSetAttribute(k_gemm<2>, cudaFuncAttributeMaxDynamicSharedMemorySize, GEMM_SMEM);
    cudaFuncSetAttribute(k_gemm<3>, cudaFuncAttributeMaxDynamicSharedMemorySize, GEMM_SMEM);

    // 0: fused build + weight prep
    k_prep<<<PREP_BUILD_BLKS + PREP_W_BLKS, 256>>>(x, b_xseq, w_in, w_mout, w_out, w_zx, w_bc,
                                                   b_winT, b_wmoutT, b_woutT, b_wcomb);
    // 1: proj GEMM (9216x768 | K=192); epilogue: projc, xssmt (tf32 silu), gsil
    k_gemm<1><<<dim3(768/128, ROWS/128), 256, GEMM_SMEM>>>(b_xseq, b_winT, b_projc,
                                                           ROWS, 768, DIMC, DIMC,
                                                           b_xssmt, b_gsil, nullptr);
    // 2: dt GEMV (fp32)
    k_dtgemv<<<ROWS/8, 256>>>(b_projc, w_dt, b_dtr);
    // 3: zx GEMM (9216x800 | K=384), split epilogue -> z / xh / bc
    k_gemm<2><<<dim3((ZXW+127)/128, ROWS/128), 256, GEMM_SMEM>>>(b_xssmt, b_wcomb, nullptr,
                                                                 ROWS, ZXW, EC, EC,
                                                                 b_z, b_xh, b_bcb);
    // 4: dt / r / cumsum
    k_dtscan<<<KC*HHC, 256>>>(b_dtr, dt_bias, A_log, b_dtb, b_rb, b_cum);
    // 5: rms + rotary (deduplicated sincos)
    k_rot<<<ROWS/8, 256>>>(b_bcb, bias_bc, theta, b_cum, b_Bt, b_Ct);
    // 6: split-sequence scan (A local, B combine, C fixup)
    k_scanA<<<dim3(KC*HHC, NSEG), 256>>>(b_Bt, b_Ct, b_xh, b_dtb, b_rb, D_skip, b_y, b_rc, b_hend);
    k_scanB<<<KC*HHC, 256>>>(b_hend, b_rc, b_hin);
    k_scanC<<<dim3(KC*HHC, NSEG), 256>>>(b_Ct, b_rc, b_hin, b_y);
    // 7: gated rms norm
    k_gate<<<(ROWS*32+255)/256, 256>>>(b_y, b_z, rms_w, b_g);
    // 8: mout GEMM (9216x384 | K=384), epilogue multiplies by gsil -> moG
    k_gemm<3><<<dim3(EC/128, ROWS/128), 256, GEMM_SMEM>>>(b_g, b_wmoutT, b_moG,
                                                          ROWS, EC, EC, EC,
                                                          b_gsil, nullptr, nullptr);
    // 9: 4-direction merge
    k_xmerge<<<(LSEQ*EC+255)/256, 256>>>(b_moG, b_mT);
    // 10: output projection GEMM (2304x192 | K=384), single launch
    k_gemm<0><<<dim3((DIMC+127)/128, LSEQ/128), 256, GEMM_SMEM>>>(b_mT, b_woutT, b_pre,
                                                                  LSEQ, DIMC, EC, EC,
                                                                  nullptr, nullptr, nullptr);
    // 11: layernorm + residual
    k_ln<<<(LSEQ*32+255)/256, 256>>>(b_pre, x, ln_g, ln_b, resscale, out);
}

// round 13
// speedup vs baseline: 1.5264x; 1.5264x over previous
#include <cuda_runtime.h>
#include <cstdint>
#include <math.h>

#define LSEQ 2304
#define DIMC 192
#define EC   384
#define NC   16
#define PC   64
#define HHC  6
#define KC   4
#define ROWS (KC*LSEQ)   /* 9216 */
#define ZXW  800         /* zx GEMM logical N: 384 z + 384 xh + 32 bc */
#define NSEG 8
#define TSEG (LSEQ/NSEG) /* 288 */

// ---------------- scratch (static device globals; no allocation) ----------------
static __device__ __align__(16) float g_xseq[ROWS*DIMC];      // tf32-rounded
static __device__ __align__(16) float g_projc[ROWS*EC];       // fp32 pre-silu (ssm half)
static __device__ __align__(16) float g_gsil [ROWS*EC];       // fp32 silu(gate half)
static __device__ __align__(16) float g_xssmt[ROWS*EC];       // tf32 silu(proj) (GEMM epi)
static __device__ __align__(16) float g_wcomb[EC*ZXW];        // tf32-rounded
static __device__ __align__(16) float g_winT[DIMC*768];       // tf32-rounded
static __device__ __align__(16) float g_wmoutT[EC*EC];        // tf32-rounded
static __device__ __align__(16) float g_woutT[EC*DIMC];       // tf32-rounded
static __device__ __align__(16) float g_z  [ROWS*EC];         // fp32 (zx epi split)
static __device__ __align__(16) float g_xh [ROWS*EC];         // fp32
static __device__ __align__(16) float g_bcb[ROWS*32];         // fp32
static __device__ __align__(16) float g_dtr[ROWS*HHC];
static __device__ __align__(16) float g_dtb[ROWS*HHC];        // 0.5*dt
static __device__ __align__(16) float g_rb[ROWS*HHC];
static __device__ __align__(16) float g_cum[ROWS*HHC];
static __device__ __align__(16) float g_Bt[ROWS*HHC*NC];
static __device__ __align__(16) float g_Ct[ROWS*HHC*NC];
static __device__ __align__(16) float g_y[ROWS*EC];
static __device__ __align__(16) float g_g[ROWS*EC];           // tf32-rounded
static __device__ __align__(16) float g_moG[ROWS*EC];         // mout * gsil (EPI 3)
static __device__ __align__(16) float g_mT[LSEQ*EC];          // tf32-rounded
static __device__ __align__(16) float g_pre[LSEQ*DIMC];
static __device__ __align__(16) float g_rc[KC*HHC*LSEQ];
static __device__ __align__(16) float g_hend[KC*HHC*NSEG*PC*NC];
static __device__ __align__(16) float g_hin[KC*HHC*NSEG*PC*NC];

__device__ __forceinline__ float siluf(float v){
    return __fdividef(v, 1.f + __expf(-v));
}
__device__ __forceinline__ float f2tf32f(float f){
    uint32_t u; asm("cvt.rna.tf32.f32 %0, %1;" : "=r"(u) : "f"(f));
    return __uint_as_float(u);
}
__device__ __forceinline__ void ldsm_x4(uint32_t &r0, uint32_t &r1, uint32_t &r2, uint32_t &r3,
                                        uint32_t addr){
    asm volatile("ldmatrix.sync.aligned.m8n8.x4.shared.b16 {%0,%1,%2,%3}, [%4];"
                 : "=r"(r0), "=r"(r1), "=r"(r2), "=r"(r3) : "r"(addr));
}

#define CP16(dst,src) asm volatile("cp.async.cg.shared.global [%0],[%1],16;\n"::"r"(dst),"l"(src))
#define CP16Z(dst,src) asm volatile("cp.async.cg.shared.global [%0],[%1],16,0;\n"::"r"(dst),"l"(src))
#define CP4(dst,src)  asm volatile("cp.async.ca.shared.global [%0],[%1],4;\n"::"r"(dst),"l"(src))
#define CPCOMMIT()    asm volatile("cp.async.commit_group;\n")
#define CPWAIT1()     asm volatile("cp.async.wait_group 1;\n")

// ---------------- fused prep: build 4-dir sequence + tf32 weight copies ----------------
#define WP1 (DIMC*768)
#define WP2 (WP1 + EC*EC)
#define WP3 (WP2 + EC*DIMC)
#define WP4 (WP3 + EC*ZXW)
#define PREP_BUILD_BLKS (DIMC*KC)   /* 768 */
#define PREP_W_BLKS ((WP4+255)/256)
__global__ __launch_bounds__(256) void k_prep(const float* __restrict__ x, float* __restrict__ xseq,
                        const float* __restrict__ w_in, const float* __restrict__ w_mout,
                        const float* __restrict__ w_out, const float* __restrict__ wzx,
                        const float* __restrict__ wbc,
                        float* __restrict__ winT, float* __restrict__ wmoutT,
                        float* __restrict__ woutT, float* __restrict__ wcomb){
    int tid = threadIdx.x;
    if (blockIdx.x < PREP_BUILD_BLKS){
        __shared__ float sm[LSEQ + LSEQ/48];
        int d = blockIdx.x >> 2;
        int k = blockIdx.x & 3;
        for (int i = tid; i < LSEQ; i += 256)
            sm[i + i/48] = x[d*LSEQ + i];
        __syncthreads();
        size_t obase = (size_t)k*(LSEQ*DIMC) + (size_t)d*LSEQ;
        for (int l = tid; l < LSEQ; l += 256){
            int m;
            if      (k==0) m = l;
            else if (k==1) m = (l%48)*48 + l/48;
            else if (k==2) m = 2303 - l;
            else { int lr = 2303-l; m = (lr%48)*48 + lr/48; }
            xseq[obase + l] = f2tf32f(sm[m + m/48]);
        }
        return;
    }
    int idx = (blockIdx.x - PREP_BUILD_BLKS)*256 + tid;
    if (idx >= WP4) return;
    if (idx < WP1){ winT[idx] = f2tf32f(w_in[idx]); return; }
    if (idx < WP2){ int i = idx-WP1; wmoutT[i] = f2tf32f(w_mout[i]); return; }
    if (idx < WP3){ int i = idx-WP2; woutT[i] = f2tf32f(w_out[i]); return; }
    int i = idx-WP3;
    int kk = i / ZXW, j = i % ZXW;
    float v = (j < 768) ? wzx[kk*768 + j] : wbc[kk*32 + (j-768)];
    wcomb[i] = f2tf32f(v);
}

// ---------------- tf32 tensor-core GEMM, BK=32, 3-stage cp.async, 1 sync/k-tile ----------------
// BM=128, BN=128. 8 warps: 2(m) x 4(n), warp tile 64x32, mma m16n8k8, A via ldmatrix.
// (R10 inner-loop form: measured best.)
#define GEMM_SMEM ((3*128*36 + 3*32*136)*4)
#define AS(b,r,c) Asp[(b)*128*36 + (r)*36 + (c)]
#define BS(b,r,c) Bsp[(b)*32*136 + (r)*136 + (c)]
template<int EPI>
__global__ __launch_bounds__(256,2) void k_gemm(const float* __restrict__ A,
                                                const float* __restrict__ B,
                                                float* __restrict__ C,
                                                int M, int N, int LDA, int KLEN,
                                                float* __restrict__ o1,
                                                float* __restrict__ o2,
                                                float* __restrict__ o3){
    extern __shared__ float dynsmem[];
    float* Asp = dynsmem;
    float* Bsp = dynsmem + 3*128*36;
    const int BM=128, BN=128, BK=32;
    int tid  = threadIdx.x;
    int warp = tid>>5, lane = tid&31;
    int wm = warp>>2, wn = warp&3;
    int gid = lane>>2, tig = lane&3;
    int bm = blockIdx.y*BM, bn = blockIdx.x*BN;

    int q = lane>>3, rl = lane&7;
    uint32_t aAddrBase = (uint32_t)__cvta_generic_to_shared(Asp)
        + (uint32_t)((((q&1)*8 + rl)*36 + (q>>1)*4) * 4)
        + (uint32_t)(wm*64*36*4);

    float acc[4][4][4];
    #pragma unroll
    for (int m=0;m<4;m++)
        #pragma unroll
        for (int n=0;n<4;n++)
            #pragma unroll
            for (int i=0;i<4;i++) acc[m][n][i]=0.f;

    auto stage = [&](int buf, int k0){
        #pragma unroll
        for (int j=0;j<4;j++){
            int i = tid + j*256;          // A: 128x32 = 1024 float4
            int r = i>>3, kc = i&7;
            uint32_t dst = (uint32_t)__cvta_generic_to_shared(&AS(buf, r, kc*4));
            CP16(dst, &A[(size_t)(bm+r)*LDA + k0 + kc*4]);
        }
        #pragma unroll
        for (int j=0;j<4;j++){
            int i = tid + j*256;          // B: 32x128 = 1024 float4
            int r = i>>5, c = i&31;
            uint32_t dst = (uint32_t)__cvta_generic_to_shared(&BS(buf, r, c*4));
            if (bn + c*4 + 4 <= N) CP16(dst, &B[(size_t)(k0+r)*N + bn + c*4]);
            else                   CP16Z(dst, B);
        }
        CPCOMMIT();
    };

    int nk = KLEN/BK;      // >= 6 for all calls
    stage(0, 0);
    stage(1, BK);
    for (int kt=0; kt<nk; ++kt){
        CPWAIT1();                     // group kt complete (kt+1 may be pending)
        __syncthreads();               // all warps done with buf[(kt-1)%3]
        if (kt+2 < nk) stage((kt+2)%3, (kt+2)*BK);   // overwrites buf[(kt-1)%3] - safe
        else CPCOMMIT();
        int buf = kt - (kt/3)*3;

        uint32_t aBufBase = aAddrBase + (uint32_t)(buf*128*36*4);
        #pragma unroll
        for (int kk=0; kk<4; kk++){
            int kb = kk*8;
            uint32_t a[4][4];
            #pragma unroll
            for (int m=0;m<4;m++){
                ldsm_x4(a[m][0], a[m][1], a[m][2], a[m][3],
                        aBufBase + (uint32_t)((m*16*36 + kb)*4));
            }
            uint32_t b[4][2];
            #pragma unroll
            for (int n=0;n<4;n++){
                int nc = wn*32 + n*8;
                b[n][0] = __float_as_uint(BS(buf, kb+tig,   nc+gid));
                b[n][1] = __float_as_uint(BS(buf, kb+tig+4, nc+gid));
            }
            #pragma unroll
            for (int m=0;m<4;m++)
                #pragma unroll
                for (int n=0;n<4;n++){
                    asm volatile(
                        "mma.sync.aligned.m16n8k8.row.col.f32.tf32.tf32.f32 "
                        "{%0,%1,%2,%3}, {%4,%5,%6,%7}, {%8,%9}, {%0,%1,%2,%3};"
                        : "+f"(acc[m][n][0]), "+f"(acc[m][n][1]),
                          "+f"(acc[m][n][2]), "+f"(acc[m][n][3])
                        : "r"(a[m][0]), "r"(a[m][1]), "r"(a[m][2]), "r"(a[m][3]),
                          "r"(b[n][0]), "r"(b[n][1]));
                }
        }
    }
    #pragma unroll
    for (int m=0;m<4;m++){
        int row0 = bm + wm*64 + m*16 + gid;
        #pragma unroll
        for (int n=0;n<4;n++){
            int col = bn + wn*32 + n*8 + tig*2;
            #pragma unroll
            for (int cc=0; cc<2; cc++){
                int cl = col + cc;
                if (cl >= N) continue;
                float v0 = acc[m][n][cc];       // row0
                float v1 = acc[m][n][2+cc];     // row0+8
                if (EPI == 0){
                    C[(size_t)row0*N + cl] = v0;
                    C[(size_t)(row0+8)*N + cl] = v1;
                } else if (EPI == 1){
                    if (cl < 384){
                        C[(size_t)row0*EC + cl] = v0;          // compact pre-silu fp32
                        C[(size_t)(row0+8)*EC + cl] = v1;
                        o1[(size_t)row0*EC + cl] = f2tf32f(siluf(v0));
                        o1[(size_t)(row0+8)*EC + cl] = f2tf32f(siluf(v1));
                    } else {
                        o2[(size_t)row0*EC + cl-384] = siluf(v0);  // gate silu fp32
                        o2[(size_t)(row0+8)*EC + cl-384] = siluf(v1);
                    }
                } else if (EPI == 2){  // split z / xh / bc
                    if (cl < 384){
                        o1[(size_t)row0*EC + cl] = v0;
                        o1[(size_t)(row0+8)*EC + cl] = v1;
                    } else if (cl < 768){
                        o2[(size_t)row0*EC + cl-384] = v0;
                        o2[(size_t)(row0+8)*EC + cl-384] = v1;
                    } else {
                        o3[(size_t)row0*32 + cl-768] = v0;
                        o3[(size_t)(row0+8)*32 + cl-768] = v1;
                    }
                } else {  // EPI == 3: C = acc * o1 (gate silu)
                    C[(size_t)row0*N + cl] = v0 * o1[(size_t)row0*EC + cl];
                    C[(size_t)(row0+8)*N + cl] = v1 * o1[(size_t)(row0+8)*EC + cl];
                }
            }
        }
    }
}

// ---------------- dt GEMV: dtr[row][h] = silu(projc[row,:])·w_dt[:,h] (fp32) ----------------
__global__ __launch_bounds__(256) void k_dtgemv(const float* __restrict__ projc,
                                                const float* __restrict__ w_dt,
                                                float* __restrict__ dtr){
    __shared__ float wst[HHC*EC];   // transposed [h][e] -> bank = lane, conflict-free
    int tid = threadIdx.x;
    for (int i=tid; i<EC*HHC; i+=256){
        int h = i % HHC, e = i / HHC;
        wst[h*EC + e] = w_dt[i];
    }
    __syncthreads();
    int warp = tid>>5, lane = tid&31;
    int row = blockIdx.x*8 + warp;
    float s[HHC];
    #pragma unroll
    for (int h=0;h<HHC;h++) s[h]=0.f;
    #pragma unroll
    for (int j=0;j<12;j++){
        int e = lane + j*32;
        float xv = siluf(projc[(size_t)row*EC + e]);
        #pragma unroll
        for (int h=0;h<HHC;h++) s[h] = fmaf(xv, wst[h*EC+e], s[h]);
    }
    #pragma unroll
    for (int h=0;h<HHC;h++){
        #pragma unroll
        for (int off=16; off>=1; off>>=1) s[h] += __shfl_xor_sync(0xffffffffu, s[h], off);
    }
    #pragma unroll
    for (int h=0;h<HHC;h++)
        if (lane == h) dtr[(size_t)row*HHC + h] = s[h];
}

// ---------------- dt path: softplus, r, cumsum (precise exp) ----------------
__global__ void k_dtscan(const float* __restrict__ dtr, const float* __restrict__ dt_bias,
                         const float* __restrict__ A_log,
                         float* __restrict__ dtb, float* __restrict__ rb, float* __restrict__ cumb){
    int k = blockIdx.x / HHC, h = blockIdx.x % HHC;
    __shared__ float part[256];
    float expA = expf(A_log[h]);
    float bias = dt_bias[h];
    int tid = threadIdx.x;
    int tbase = tid*9;
    float loc[9]; float s = 0.f;
    #pragma unroll
    for (int i=0;i<9;i++){
        size_t row = (size_t)k*LSEQ + tbase + i;
        float v  = dtr[row*HHC + h] + bias;
        float dt = (v > 20.f) ? v : log1pf(expf(v));
        dtb[row*HHC+h] = 0.5f*dt;
        rb [row*HHC+h] = expf(-dt*expA);
        s += dt; loc[i] = s;
    }
    part[tid] = s; __syncthreads();
    for (int off=1; off<256; off<<=1){
        float add = (tid >= off) ? part[tid-off] : 0.f;
        __syncthreads();
        part[tid] += add;
        __syncthreads();
    }
    float offset = part[tid] - s;
    #pragma unroll
    for (int i=0;i<9;i++){
        size_t row = (size_t)k*LSEQ + tbase + i;
        cumb[row*HHC+h] = loc[i] + offset;
    }
}

// ---------------- rms(B/C) + rotary: warp per row, deduplicated sincos ----------------
__global__ __launch_bounds__(256) void k_rot(const float* __restrict__ bcb, const float* __restrict__ bias_bc,
                                             const float* __restrict__ theta, const float* __restrict__ cumb,
                                             float* __restrict__ Bt, float* __restrict__ Ct){
    int row  = (blockIdx.x*blockDim.x + threadIdx.x) >> 5;
    int lane = threadIdx.x & 31;
    if (row >= ROWS) return;
    float bc = bcb[(size_t)row*32 + lane] + bias_bc[lane];
    float s = bc*bc;
    s += __shfl_xor_sync(0xffffffffu, s, 1);
    s += __shfl_xor_sync(0xffffffffu, s, 2);
    s += __shfl_xor_sync(0xffffffffu, s, 4);
    s += __shfl_xor_sync(0xffffffffu, s, 8);
    float rn = rsqrtf(s*(1.f/16.f) + 1e-6f);
    float v = bc * rn;

    float cval = (lane < HHC) ? cumb[(size_t)row*HHC + lane] : 0.f;
    float th0 = theta[lane];
    float th1 = (lane < 16) ? theta[32 + lane] : 0.f;
    float cd0 = __shfl_sync(0xffffffffu, cval, lane>>3);
    float cd1 = __shfl_sync(0xffffffffu, cval, 4 + (lane>>3));
    float s0, c0, s1, c1;
    sincosf(cd0*th0, &s0, &c0);
    sincosf(cd1*th1, &s1, &c1);

    int j = lane & 15;
    int half = lane & 16;
    int i = j >> 1;
    float v0 = __shfl_sync(0xffffffffu, v, half + 2*i);
    float v1 = __shfl_sync(0xffffffffu, v, half + 2*i + 1);
    bool odd = (j & 1) != 0;
    #pragma unroll
    for (int h=0; h<HHC; h++){
        int p = h*8 + i;
        float cc = (h < 4) ? __shfl_sync(0xffffffffu, c0, p)
                           : __shfl_sync(0xffffffffu, c1, p - 32);
        float ss = (h < 4) ? __shfl_sync(0xffffffffu, s0, p)
                           : __shfl_sync(0xffffffffu, s1, p - 32);
        float o = odd ? fmaf(-v0, ss, v1*cc) : fmaf(v0, cc, v1*ss);
        float* dst = half ? Ct : Bt;
        dst[((size_t)row*HHC + h)*16 + j] = o;
    }
}

// ---------------- scan phase A: per-segment local scan (h_in = 0) ----------------
#define SCH 32
__global__ __launch_bounds__(256) void k_scanA(const float* __restrict__ Bt, const float* __restrict__ Ct,
                                               const float* __restrict__ xh, const float* __restrict__ dtb,
                                               const float* __restrict__ rb, const float* __restrict__ Dsk,
                                               float* __restrict__ y, float* __restrict__ rc,
                                               float* __restrict__ hend){
    __shared__ __align__(16) float Bs[2][SCH][16];
    __shared__ __align__(16) float Cs[2][SCH][16];
    __shared__ __align__(16) float Xs[2][SCH][64];
    __shared__ float Ds[2][SCH];
    __shared__ float Rs[2][SCH];
    __shared__ __align__(16) float Ys[SCH][64];
    __shared__ float Rys[SCH];

    int kh = blockIdx.x; int k = kh/HHC, h = kh%HHC;
    int seg = blockIdx.y;
    int tseg0 = seg*TSEG;
    int tid = threadIdx.x;
    int p = tid>>2, ng = tid&3;
    size_t bBase = ((size_t)k*LSEQ*HHC + h)*16;
    size_t xBase = (size_t)k*LSEQ*EC + (size_t)h*64;
    size_t sBase = (size_t)k*LSEQ*HHC + h;
    float dsk = Dsk[h];
    float* ybase = y + (size_t)k*LSEQ*EC + h*64;
    size_t rcBase = (size_t)kh*LSEQ;

    auto stage = [&](int buf, int t0){
        {
            int id = tid & 127;
            int tl = id>>2, sg = id&3;
            size_t off = bBase + (size_t)(t0+tl)*96 + sg*4;
            if (tid < 128){
                uint32_t d = (uint32_t)__cvta_generic_to_shared(&Bs[buf][tl][sg*4]);
                CP16(d, &Bt[off]);
            } else {
                uint32_t d = (uint32_t)__cvta_generic_to_shared(&Cs[buf][tl][sg*4]);
                CP16(d, &Ct[off]);
            }
        }
        #pragma unroll
        for (int j=0;j<2;j++){
            int i = tid + j*256;
            int tl = i>>4, c = i&15;
            uint32_t d = (uint32_t)__cvta_generic_to_shared(&Xs[buf][tl][c*4]);
            CP16(d, &xh[xBase + (size_t)(t0+tl)*EC + c*4]);
        }
        if (tid < SCH){
            uint32_t d = (uint32_t)__cvta_generic_to_shared(&Ds[buf][tid]);
            CP4(d, &dtb[sBase + (size_t)(t0+tid)*HHC]);
        } else if (tid < 2*SCH){
            int tl = tid - SCH;
            uint32_t d = (uint32_t)__cvta_generic_to_shared(&Rs[buf][tl]);
            CP4(d, &rb[sBase + (size_t)(t0+tl)*HHC]);
        }
        CPCOMMIT();
    };

    float hs0=0.f,hs1=0.f,hs2=0.f,hs3=0.f;
    float bx0=0.f,bx1=0.f,bx2=0.f,bx3=0.f;
    if (seg > 0){
        int tp = tseg0 - 1;
        float4 Bp = *(const float4*)&Bt[bBase + (size_t)tp*96 + ng*4];
        float xp = xh[xBase + (size_t)tp*EC + p];
        bx0 = Bp.x*xp; bx1 = Bp.y*xp; bx2 = Bp.z*xp; bx3 = Bp.w*xp;
    }
    float rp = 1.f;

    stage(0, tseg0);
    const int NCHUNK = TSEG/SCH;   // 9
    for (int c=0; c<NCHUNK; ++c){
        int buf = c&1;
        if (c+1 < NCHUNK) stage(buf^1, tseg0 + (c+1)*SCH);
        else CPCOMMIT();
        CPWAIT1();
        __syncthreads();

        #pragma unroll 4
        for (int t=0; t<SCH; ++t){
            float4 Bv = *(const float4*)&Bs[buf][t][ng*4];
            float4 Cv = *(const float4*)&Cs[buf][t][ng*4];
            float xv = Xs[buf][t][p];
            float ad = Ds[buf][t];
            float rv = Rs[buf][t];
            float G0 = Bv.x*xv, G1 = Bv.y*xv, G2 = Bv.z*xv, G3 = Bv.w*xv;
            float u0 = fmaf(rv,bx0,G0), u1 = fmaf(rv,bx1,G1);
            float u2 = fmaf(rv,bx2,G2), u3 = fmaf(rv,bx3,G3);
            hs0 = fmaf(rv,hs0,ad*u0); hs1 = fmaf(rv,hs1,ad*u1);
            hs2 = fmaf(rv,hs2,ad*u2); hs3 = fmaf(rv,hs3,ad*u3);
            bx0=G0; bx1=G1; bx2=G2; bx3=G3;
            rp *= rv;
            float v = fmaf(Cv.x,hs0, fmaf(Cv.y,hs1, fmaf(Cv.z,hs2, Cv.w*hs3)));
            v += __shfl_xor_sync(0xffffffffu, v, 1);
            v += __shfl_xor_sync(0xffffffffu, v, 2);
            if (ng == 0) Ys[t][p] = fmaf(dsk, xv, v);
            if (tid == 0) Rys[t] = rp;
        }
        __syncthreads();
        int t0 = tseg0 + c*SCH;
        #pragma unroll
        for (int j=0;j<2;j++){
            int i = tid + j*256;
            int tl = i>>4, cc = i&15;
            *(float4*)&ybase[(size_t)(t0+tl)*EC + cc*4] = *(const float4*)&Ys[tl][cc*4];
        }
        if (tid < SCH) rc[rcBase + t0 + tid] = Rys[tid];
    }
    float4 he = make_float4(hs0,hs1,hs2,hs3);
    *(float4*)&hend[(((size_t)kh*NSEG + seg)*PC + p)*NC + ng*4] = he;
}

// ---------------- scan phase B: sequential combine of segment boundary states ----------------
__global__ __launch_bounds__(256) void k_scanB(const float* __restrict__ hend,
                                               const float* __restrict__ rc,
                                               float* __restrict__ hin){
    int kh = blockIdx.x;
    int tid = threadIdx.x;
    int p = tid>>2, ng = tid&3;
    float4 hi = make_float4(0.f,0.f,0.f,0.f);
    #pragma unroll
    for (int s=0; s<NSEG; ++s){
        size_t idx = (((size_t)kh*NSEG + s)*PC + p)*NC + ng*4;
        *(float4*)&hin[idx] = hi;
        float4 he = *(const float4*)&hend[idx];
        float Rseg = rc[(size_t)kh*LSEQ + s*TSEG + TSEG-1];
        hi.x = fmaf(Rseg, hi.x, he.x);
        hi.y = fmaf(Rseg, hi.y, he.y);
        hi.z = fmaf(Rseg, hi.z, he.z);
        hi.w = fmaf(Rseg, hi.w, he.w);
    }
}

// ---------------- scan phase C: fixup y += R(t) * (C_t · h_in) ----------------
__global__ __launch_bounds__(256) void k_scanC(const float* __restrict__ Ct,
                                               const float* __restrict__ rc,
                                               const float* __restrict__ hin,
                                               float* __restrict__ y){
    int seg = blockIdx.y;
    if (seg == 0) return;
    __shared__ float Hs[PC][NC+1];
    __shared__ float Cs[SCH][NC+1];
    __shared__ float Rsh[SCH];
    int kh = blockIdx.x; int k = kh/HHC, h = kh%HHC;
    int tid = threadIdx.x;
    int p = tid&63, tq = tid>>6;
    size_t hBase = ((size_t)kh*NSEG + seg)*PC*NC;
    for (int i=tid; i<PC*NC; i+=256) Hs[i>>4][i&15] = hin[hBase + i];
    __syncthreads();
    float hn[NC];
    #pragma unroll
    for (int i=0;i<NC;i++) hn[i] = Hs[p][i];

    size_t bBase = ((size_t)k*LSEQ*HHC + h)*16;
    size_t rcBase = (size_t)kh*LSEQ;
    float* ybase = y + (size_t)k*LSEQ*EC + h*64;
    int tseg0 = seg*TSEG;

    for (int c=0; c<TSEG/SCH; ++c){
        int t0 = tseg0 + c*SCH;
        for (int i=tid; i<SCH*NC; i+=256){
            int tl = i>>4, nn = i&15;
            Cs[tl][nn] = Ct[bBase + (size_t)(t0+tl)*96 + nn];
        }
        if (tid < SCH) Rsh[tid] = rc[rcBase + t0 + tid];
        __syncthreads();
        if (Rsh[0] == 0.f) break;
        #pragma unroll
        for (int jt=0; jt<SCH/4; ++jt){
            int tl = tq + jt*4;
            float R = Rsh[tl];
            if (R != 0.f){
                float corr = 0.f;
                #pragma unroll
                for (int i=0;i<NC;i++) corr = fmaf(Cs[tl][i], hn[i], corr);
                ybase[(size_t)(t0+tl)*EC + p] += R*corr;
            }
        }
        __syncthreads();
    }
}

// ---------------- g = tf32(rms(y * silu(z)) * rms_w)  (warp per row, compact z) ----------------
__global__ void k_gate(const float* __restrict__ y, const float* __restrict__ z,
                       const float* __restrict__ rms_w, float* __restrict__ g){
    int warp = (blockIdx.x*blockDim.x + threadIdx.x) >> 5;
    int lane = threadIdx.x & 31;
    if (warp >= ROWS) return;
    size_t base = (size_t)warp*EC;
    float v[12]; float s2 = 0.f;
    #pragma unroll
    for (int j=0;j<12;j++){
        int e = lane + j*32;
        float t = y[base + e] * siluf(z[base + e]);
        v[j] = t; s2 += t*t;
    }
    #pragma unroll
    for (int off=16; off>=1; off>>=1) s2 += __shfl_xor_sync(0xffffffffu, s2, off);
    float rn = rsqrtf(s2*(1.f/384.f) + 1e-6f);
    #pragma unroll
    for (int j=0;j<12;j++){
        int e = lane + j*32;
        g[base + e] = f2tf32f(v[j]*rn*rms_w[e]);
    }
}

// ---------------- merge 4 dirs of moG -> mT (tf32) ----------------
__global__ void k_xmerge(const float* __restrict__ moG, float* __restrict__ mT){
    int idx = blockIdx.x*blockDim.x + threadIdx.x;
    if (idx >= LSEQ*EC) return;
    int l = idx / EC, e = idx % EC;
    int lt = (l%48)*48 + l/48;
    size_t r0 = (size_t)l*EC + e;
    size_t r1 = (size_t)(LSEQ + lt)*EC + e;
    size_t r2 = (size_t)(2*LSEQ + 2303 - l)*EC + e;
    size_t r3 = (size_t)(3*LSEQ + 2303 - lt)*EC + e;
    mT[idx] = f2tf32f(moG[r0] + moG[r1] + moG[r2] + moG[r3]);
}

// ---------------- LayerNorm + residual ----------------
__global__ void k_ln(const float* __restrict__ pre, const float* __restrict__ x,
                     const float* __restrict__ ln_g, const float* __restrict__ ln_b,
                     const float* __restrict__ res_scale, float* __restrict__ out){
    int warp = (blockIdx.x*blockDim.x + threadIdx.x) >> 5;
    int lane = threadIdx.x & 31;
    if (warp >= LSEQ) return;
    int l = warp;
    float v[6]; float s = 0.f;
    #pragma unroll
    for (int j=0;j<6;j++){ v[j] = pre[(size_t)l*DIMC + lane + j*32]; s += v[j]; }
    #pragma unroll
    for (int off=16; off>=1; off>>=1) s += __shfl_xor_sync(0xffffffffu, s, off);
    float mu = s*(1.f/192.f);
    float q = 0.f;
    #pragma unroll
    for (int j=0;j<6;j++){ float d = v[j]-mu; q += d*d; }
    #pragma unroll
    for (int off=16; off>=1; off>>=1) q += __shfl_xor_sync(0xffffffffu, q, off);
    float inv = rsqrtf(q*(1.f/192.f) + 1e-5f);
    float rs = res_scale[0];
    #pragma unroll
    for (int j=0;j<6;j++){
        int d = lane + j*32;
        out[(size_t)d*LSEQ + l] = x[(size_t)d*LSEQ + l]
            + rs*((v[j]-mu)*inv*ln_g[d] + ln_b[d]);
    }
}

// ---------------- launch ----------------
extern "C" void kernel_launch(void* const* d_in, const int* in_sizes, int n_in,
                              void* d_out, int out_size){
    (void)in_sizes; (void)n_in; (void)out_size;
    const float* x        = (const float*)d_in[0];
    const float* w_in     = (const float*)d_in[1];
    const float* w_zx     = (const float*)d_in[2];
    const float* w_bc     = (const float*)d_in[3];
    const float* bias_bc  = (const float*)d_in[4];
    const float* w_dt     = (const float*)d_in[5];
    const float* dt_bias  = (const float*)d_in[6];
    const float* A_log    = (const float*)d_in[7];
    const float* theta    = (const float*)d_in[8];
    const float* D_skip   = (const float*)d_in[9];
    const float* rms_w    = (const float*)d_in[10];
    const float* w_mout   = (const float*)d_in[11];
    const float* w_out    = (const float*)d_in[12];
    const float* ln_g     = (const float*)d_in[13];
    const float* ln_b     = (const float*)d_in[14];
    const float* resscale = (const float*)d_in[15];
    float* out = (float*)d_out;

    float *b_xseq,*b_projc,*b_gsil,*b_xssmt,*b_wcomb,*b_winT,*b_wmoutT,*b_woutT;
    float *b_z,*b_xh,*b_bcb,*b_dtr,*b_dtb,*b_rb,*b_cum,*b_Bt,*b_Ct,*b_y,*b_g,*b_moG,*b_mT,*b_pre;
    float *b_rc,*b_hend,*b_hin;
    cudaGetSymbolAddress((void**)&b_xseq,  g_xseq);
    cudaGetSymbolAddress((void**)&b_projc, g_projc);
    cudaGetSymbolAddress((void**)&b_gsil,  g_gsil);
    cudaGetSymbolAddress((void**)&b_xssmt, g_xssmt);
    cudaGetSymbolAddress((void**)&b_wcomb, g_wcomb);
    cudaGetSymbolAddress((void**)&b_winT,  g_winT);
    cudaGetSymbolAddress((void**)&b_wmoutT,g_wmoutT);
    cudaGetSymbolAddress((void**)&b_woutT, g_woutT);
    cudaGetSymbolAddress((void**)&b_z,     g_z);
    cudaGetSymbolAddress((void**)&b_xh,    g_xh);
    cudaGetSymbolAddress((void**)&b_bcb,   g_bcb);
    cudaGetSymbolAddress((void**)&b_dtr,   g_dtr);
    cudaGetSymbolAddress((void**)&b_dtb,   g_dtb);
    cudaGetSymbolAddress((void**)&b_rb,    g_rb);
    cudaGetSymbolAddress((void**)&b_cum,   g_cum);
    cudaGetSymbolAddress((void**)&b_Bt,    g_Bt);
    cudaGetSymbolAddress((void**)&b_Ct,    g_Ct);
    cudaGetSymbolAddress((void**)&b_y,     g_y);
    cudaGetSymbolAddress((void**)&b_g,     g_g);
    cudaGetSymbolAddress((void**)&b_moG,   g_moG);
    cudaGetSymbolAddress((void**)&b_mT,    g_mT);
    cudaGetSymbolAddress((void**)&b_pre,   g_pre);
    cudaGetSymbolAddress((void**)&b_rc,    g_rc);
    cudaGetSymbolAddress((void**)&b_hend,  g_hend);
    cudaGetSymbolAddress((void**)&b_hin,   g_hin);

    cudaFuncSetAttribute(k_gemm<0>, cudaFuncAttributeMaxDynamicSharedMemorySize, GEMM_SMEM);
    cudaFuncSetAttribute(k_gemm<1>, cudaFuncAttributeMaxDynamicSharedMemorySize, GEMM_SMEM);
    cudaFuncSetAttribute(k_gemm<2>, cudaFuncAttributeMaxDynamicSharedMemorySize, GEMM_SMEM);
    cudaFuncSetAttribute(k_gemm<3>, cudaFuncAttributeMaxDynamicSharedMemorySize, GEMM_SMEM);

    // 0: fused build + weight prep
    k_prep<<<PREP_BUILD_BLKS + PREP_W_BLKS, 256>>>(x, b_xseq, w_in, w_mout, w_out, w_zx, w_bc,
                                                   b_winT, b_wmoutT, b_woutT, b_wcomb);
    // 1: proj GEMM (9216x768 | K=192); epilogue: projc, xssmt (tf32 silu), gsil
    k_gemm<1><<<dim3(768/128, ROWS/128), 256, GEMM_SMEM>>>(b_xseq, b_winT, b_projc,
                                                           ROWS, 768, DIMC, DIMC,
                                                           b_xssmt, b_gsil, nullptr);
    // 2: dt GEMV (fp32)
    k_dtgemv<<<ROWS/8, 256>>>(b_projc, w_dt, b_dtr);
    // 3: zx GEMM (9216x800 | K=384), split epilogue -> z / xh / bc
    k_gemm<2><<<dim3((ZXW+127)/128, ROWS/128), 256, GEMM_SMEM>>>(b_xssmt, b_wcomb, nullptr,
                                                                 ROWS, ZXW, EC, EC,
                                                                 b_z, b_xh, b_bcb);
    // 4: dt / r / cumsum
    k_dtscan<<<KC*HHC, 256>>>(b_dtr, dt_bias, A_log, b_dtb, b_rb, b_cum);
    // 5: rms + rotary (deduplicated sincos)
    k_rot<<<ROWS/8, 256>>>(b_bcb, bias_bc, theta, b_cum, b_Bt, b_Ct);
    // 6: split-sequence scan (A local, B combine, C fixup)
    k_scanA<<<dim3(KC*HHC, NSEG), 256>>>(b_Bt, b_Ct, b_xh, b_dtb, b_rb, D_skip, b_y, b_rc, b_hend);
    k_scanB<<<KC*HHC, 256>>>(b_hend, b_rc, b_hin);
    k_scanC<<<dim3(KC*HHC, NSEG), 256>>>(b_Ct, b_rc, b_hin, b_y);
    // 7: gated rms norm
    k_gate<<<(ROWS*32+255)/256, 256>>>(b_y, b_z, rms_w, b_g);
    // 8: mout GEMM (9216x384 | K=384), epilogue multiplies by gsil -> moG
    k_gemm<3><<<dim3(EC/128, ROWS/128), 256, GEMM_SMEM>>>(b_g, b_wmoutT, b_moG,
                                                          ROWS, EC, EC, EC,
                                                          b_gsil, nullptr, nullptr);
    // 9: 4-direction merge
    k_xmerge<<<(LSEQ*EC+255)/256, 256>>>(b_moG, b_mT);
    // 10: output projection GEMM (2304x192 | K=384), single launch
    k_gemm<0><<<dim3((DIMC+127)/128, LSEQ/128), 256, GEMM_SMEM>>>(b_mT, b_woutT, b_pre,
                                                                  LSEQ, DIMC, EC, EC,
                                                                  nullptr, nullptr, nullptr);
    // 11: layernorm + residual
    k_ln<<<(LSEQ*32+255)/256, 256>>>(b_pre, x, ln_g, ln_b, resscale, out);
}

// round 14
// speedup vs baseline: 1.5660x; 1.0260x over previous
#include <cuda_runtime.h>
#include <cstdint>
#include <math.h>

#define LSEQ 2304
#define DIMC 192
#define EC   384
#define NC   16
#define PC   64
#define HHC  6
#define KC   4
#define ROWS (KC*LSEQ)   /* 9216 */
#define ZXW  800         /* zx GEMM logical N: 384 z + 384 xh + 32 bc */
#define NSEG 8
#define TSEG (LSEQ/NSEG) /* 288 */

// ---------------- scratch (static device globals; no allocation) ----------------
static __device__ __align__(16) float g_xseq[ROWS*DIMC];      // tf32-rounded
static __device__ __align__(16) float g_projc[ROWS*EC];       // fp32 pre-silu (ssm half)
static __device__ __align__(16) float g_gsil [ROWS*EC];       // fp32 silu(gate half)
static __device__ __align__(16) float g_xssmt[ROWS*EC];       // tf32 silu(proj) (GEMM epi)
static __device__ __align__(16) float g_wcomb[EC*ZXW];        // tf32-rounded
static __device__ __align__(16) float g_winT[DIMC*768];       // tf32-rounded
static __device__ __align__(16) float g_wmoutT[EC*EC];        // tf32-rounded
static __device__ __align__(16) float g_woutT[EC*DIMC];       // tf32-rounded
static __device__ __align__(16) float g_z  [ROWS*EC];         // fp32 (zx epi split)
static __device__ __align__(16) float g_xh [ROWS*EC];         // fp32
static __device__ __align__(16) float g_bcb[ROWS*32];         // fp32
static __device__ __align__(16) float g_dtr[ROWS*HHC];
static __device__ __align__(16) float g_dtb[ROWS*HHC];        // 0.5*dt
static __device__ __align__(16) float g_rb[ROWS*HHC];
static __device__ __align__(16) float g_cum[ROWS*HHC];
static __device__ __align__(16) float g_Bt[ROWS*HHC*NC];
static __device__ __align__(16) float g_Ct[ROWS*HHC*NC];
static __device__ __align__(16) float g_y[ROWS*EC];
static __device__ __align__(16) float g_g[ROWS*EC];           // tf32-rounded
static __device__ __align__(16) float g_moG[ROWS*EC];         // mout * gsil (EPI 3)
static __device__ __align__(16) float g_mT[LSEQ*EC];          // tf32-rounded
static __device__ __align__(16) float g_pre[LSEQ*DIMC];
static __device__ __align__(16) float g_rc[KC*HHC*LSEQ];
static __device__ __align__(16) float g_hend[KC*HHC*NSEG*PC*NC];
static __device__ __align__(16) float g_hin[KC*HHC*NSEG*PC*NC];

// ---------------- side stream + fork/join events (created at load; no dev mem) ----
struct StreamInit {
    cudaStream_t s; cudaEvent_t evF, evJ;
    StreamInit(){
        cudaStreamCreateWithFlags(&s, cudaStreamNonBlocking);
        cudaEventCreateWithFlags(&evF, cudaEventDisableTiming);
        cudaEventCreateWithFlags(&evJ, cudaEventDisableTiming);
    }
};
static StreamInit g_si;

__device__ __forceinline__ float siluf(float v){
    return __fdividef(v, 1.f + __expf(-v));
}
__device__ __forceinline__ float f2tf32f(float f){
    uint32_t u; asm("cvt.rna.tf32.f32 %0, %1;" : "=r"(u) : "f"(f));
    return __uint_as_float(u);
}
__device__ __forceinline__ void ldsm_x4(uint32_t &r0, uint32_t &r1, uint32_t &r2, uint32_t &r3,
                                        uint32_t addr){
    asm volatile("ldmatrix.sync.aligned.m8n8.x4.shared.b16 {%0,%1,%2,%3}, [%4];"
                 : "=r"(r0), "=r"(r1), "=r"(r2), "=r"(r3) : "r"(addr));
}

#define CP16(dst,src) asm volatile("cp.async.cg.shared.global [%0],[%1],16;\n"::"r"(dst),"l"(src))
#define CP16Z(dst,src) asm volatile("cp.async.cg.shared.global [%0],[%1],16,0;\n"::"r"(dst),"l"(src))
#define CP4(dst,src)  asm volatile("cp.async.ca.shared.global [%0],[%1],4;\n"::"r"(dst),"l"(src))
#define CPCOMMIT()    asm volatile("cp.async.commit_group;\n")
#define CPWAIT1()     asm volatile("cp.async.wait_group 1;\n")

// ---------------- fused prep: build 4-dir sequence + tf32 weight copies ----------------
#define WP1 (DIMC*768)
#define WP2 (WP1 + EC*EC)
#define WP3 (WP2 + EC*DIMC)
#define WP4 (WP3 + EC*ZXW)
#define PREP_BUILD_BLKS (DIMC*KC)   /* 768 */
#define PREP_W_BLKS ((WP4+255)/256)
__global__ __launch_bounds__(256) void k_prep(const float* __restrict__ x, float* __restrict__ xseq,
                        const float* __restrict__ w_in, const float* __restrict__ w_mout,
                        const float* __restrict__ w_out, const float* __restrict__ wzx,
                        const float* __restrict__ wbc,
                        float* __restrict__ winT, float* __restrict__ wmoutT,
                        float* __restrict__ woutT, float* __restrict__ wcomb){
    int tid = threadIdx.x;
    if (blockIdx.x < PREP_BUILD_BLKS){
        __shared__ float sm[LSEQ + LSEQ/48];
        int d = blockIdx.x >> 2;
        int k = blockIdx.x & 3;
        for (int i = tid; i < LSEQ; i += 256)
            sm[i + i/48] = x[d*LSEQ + i];
        __syncthreads();
        size_t obase = (size_t)k*(LSEQ*DIMC) + (size_t)d*LSEQ;
        for (int l = tid; l < LSEQ; l += 256){
            int m;
            if      (k==0) m = l;
            else if (k==1) m = (l%48)*48 + l/48;
            else if (k==2) m = 2303 - l;
            else { int lr = 2303-l; m = (lr%48)*48 + lr/48; }
            xseq[obase + l] = f2tf32f(sm[m + m/48]);
        }
        return;
    }
    int idx = (blockIdx.x - PREP_BUILD_BLKS)*256 + tid;
    if (idx >= WP4) return;
    if (idx < WP1){ winT[idx] = f2tf32f(w_in[idx]); return; }
    if (idx < WP2){ int i = idx-WP1; wmoutT[i] = f2tf32f(w_mout[i]); return; }
    if (idx < WP3){ int i = idx-WP2; woutT[i] = f2tf32f(w_out[i]); return; }
    int i = idx-WP3;
    int kk = i / ZXW, j = i % ZXW;
    float v = (j < 768) ? wzx[kk*768 + j] : wbc[kk*32 + (j-768)];
    wcomb[i] = f2tf32f(v);
}

// ---------------- tf32 tensor-core GEMM, BK=32, 3-stage cp.async, 1 sync/k-tile ----------------
// BM=128, BN=128. 8 warps: 2(m) x 4(n), warp tile 64x32, mma m16n8k8, A via ldmatrix.
// Fully-OOB warp-tiles (bn + wn*32 >= N) skip fragment loads + MMAs (uniform per warp).
#define GEMM_SMEM ((3*128*36 + 3*32*136)*4)
#define AS(b,r,c) Asp[(b)*128*36 + (r)*36 + (c)]
#define BS(b,r,c) Bsp[(b)*32*136 + (r)*136 + (c)]
template<int EPI>
__global__ __launch_bounds__(256,2) void k_gemm(const float* __restrict__ A,
                                                const float* __restrict__ B,
                                                float* __restrict__ C,
                                                int M, int N, int LDA, int KLEN,
                                                float* __restrict__ o1,
                                                float* __restrict__ o2,
                                                float* __restrict__ o3){
    extern __shared__ float dynsmem[];
    float* Asp = dynsmem;
    float* Bsp = dynsmem + 3*128*36;
    const int BM=128, BN=128, BK=32;
    int tid  = threadIdx.x;
    int warp = tid>>5, lane = tid&31;
    int wm = warp>>2, wn = warp&3;
    int gid = lane>>2, tig = lane&3;
    int bm = blockIdx.y*BM, bn = blockIdx.x*BN;
    bool wActive = (bn + wn*32) < N;   // uniform per warp

    int q = lane>>3, rl = lane&7;
    uint32_t aAddrBase = (uint32_t)__cvta_generic_to_shared(Asp)
        + (uint32_t)((((q&1)*8 + rl)*36 + (q>>1)*4) * 4)
        + (uint32_t)(wm*64*36*4);

    float acc[4][4][4];
    #pragma unroll
    for (int m=0;m<4;m++)
        #pragma unroll
        for (int n=0;n<4;n++)
            #pragma unroll
            for (int i=0;i<4;i++) acc[m][n][i]=0.f;

    auto stage = [&](int buf, int k0){
        #pragma unroll
        for (int j=0;j<4;j++){
            int i = tid + j*256;          // A: 128x32 = 1024 float4
            int r = i>>3, kc = i&7;
            uint32_t dst = (uint32_t)__cvta_generic_to_shared(&AS(buf, r, kc*4));
            CP16(dst, &A[(size_t)(bm+r)*LDA + k0 + kc*4]);
        }
        #pragma unroll
        for (int j=0;j<4;j++){
            int i = tid + j*256;          // B: 32x128 = 1024 float4
            int r = i>>5, c = i&31;
            uint32_t dst = (uint32_t)__cvta_generic_to_shared(&BS(buf, r, c*4));
            if (bn + c*4 + 4 <= N) CP16(dst, &B[(size_t)(k0+r)*N + bn + c*4]);
            else                   CP16Z(dst, B);
        }
        CPCOMMIT();
    };

    int nk = KLEN/BK;      // >= 6 for all calls
    stage(0, 0);
    stage(1, BK);
    for (int kt=0; kt<nk; ++kt){
        CPWAIT1();                     // group kt complete (kt+1 may be pending)
        __syncthreads();               // all warps done with buf[(kt-1)%3]
        if (kt+2 < nk) stage((kt+2)%3, (kt+2)*BK);   // overwrites buf[(kt-1)%3] - safe
        else CPCOMMIT();
        int buf = kt - (kt/3)*3;

        if (wActive){
            uint32_t aBufBase = aAddrBase + (uint32_t)(buf*128*36*4);
            #pragma unroll
            for (int kk=0; kk<4; kk++){
                int kb = kk*8;
                uint32_t a[4][4];
                #pragma unroll
                for (int m=0;m<4;m++){
                    ldsm_x4(a[m][0], a[m][1], a[m][2], a[m][3],
                            aBufBase + (uint32_t)((m*16*36 + kb)*4));
                }
                uint32_t b[4][2];
                #pragma unroll
                for (int n=0;n<4;n++){
                    int nc = wn*32 + n*8;
                    b[n][0] = __float_as_uint(BS(buf, kb+tig,   nc+gid));
                    b[n][1] = __float_as_uint(BS(buf, kb+tig+4, nc+gid));
                }
                #pragma unroll
                for (int m=0;m<4;m++)
                    #pragma unroll
                    for (int n=0;n<4;n++){
                        asm volatile(
                            "mma.sync.aligned.m16n8k8.row.col.f32.tf32.tf32.f32 "
                            "{%0,%1,%2,%3}, {%4,%5,%6,%7}, {%8,%9}, {%0,%1,%2,%3};"
                            : "+f"(acc[m][n][0]), "+f"(acc[m][n][1]),
                              "+f"(acc[m][n][2]), "+f"(acc[m][n][3])
                            : "r"(a[m][0]), "r"(a[m][1]), "r"(a[m][2]), "r"(a[m][3]),
                              "r"(b[n][0]), "r"(b[n][1]));
                    }
            }
        }
    }
    if (!wActive) return;
    #pragma unroll
    for (int m=0;m<4;m++){
        int row0 = bm + wm*64 + m*16 + gid;
        #pragma unroll
        for (int n=0;n<4;n++){
            int col = bn + wn*32 + n*8 + tig*2;
            #pragma unroll
            for (int cc=0; cc<2; cc++){
                int cl = col + cc;
                if (cl >= N) continue;
                float v0 = acc[m][n][cc];       // row0
                float v1 = acc[m][n][2+cc];     // row0+8
                if (EPI == 0){
                    C[(size_t)row0*N + cl] = v0;
                    C[(size_t)(row0+8)*N + cl] = v1;
                } else if (EPI == 1){
                    if (cl < 384){
                        C[(size_t)row0*EC + cl] = v0;          // compact pre-silu fp32
                        C[(size_t)(row0+8)*EC + cl] = v1;
                        o1[(size_t)row0*EC + cl] = f2tf32f(siluf(v0));
                        o1[(size_t)(row0+8)*EC + cl] = f2tf32f(siluf(v1));
                    } else {
                        o2[(size_t)row0*EC + cl-384] = siluf(v0);  // gate silu fp32
                        o2[(size_t)(row0+8)*EC + cl-384] = siluf(v1);
                    }
                } else if (EPI == 2){  // split z / xh / bc
                    if (cl < 384){
                        o1[(size_t)row0*EC + cl] = v0;
                        o1[(size_t)(row0+8)*EC + cl] = v1;
                    } else if (cl < 768){
                        o2[(size_t)row0*EC + cl-384] = v0;
                        o2[(size_t)(row0+8)*EC + cl-384] = v1;
                    } else {
                        o3[(size_t)row0*32 + cl-768] = v0;
                        o3[(size_t)(row0+8)*32 + cl-768] = v1;
                    }
                } else {  // EPI == 3: C = acc * o1 (gate silu)
                    C[(size_t)row0*N + cl] = v0 * o1[(size_t)row0*EC + cl];
                    C[(size_t)(row0+8)*N + cl] = v1 * o1[(size_t)(row0+8)*EC + cl];
                }
            }
        }
    }
}

// ---------------- dt GEMV: dtr[row][h] = silu(projc[row,:])·w_dt[:,h] (fp32) ----------------
__global__ __launch_bounds__(256) void k_dtgemv(const float* __restrict__ projc,
                                                const float* __restrict__ w_dt,
                                                float* __restrict__ dtr){
    __shared__ float wst[HHC*EC];   // transposed [h][e] -> bank = lane, conflict-free
    int tid = threadIdx.x;
    for (int i=tid; i<EC*HHC; i+=256){
        int h = i % HHC, e = i / HHC;
        wst[h*EC + e] = w_dt[i];
    }
    __syncthreads();
    int warp = tid>>5, lane = tid&31;
    int row = blockIdx.x*8 + warp;
    float s[HHC];
    #pragma unroll
    for (int h=0;h<HHC;h++) s[h]=0.f;
    #pragma unroll
    for (int j=0;j<12;j++){
        int e = lane + j*32;
        float xv = siluf(projc[(size_t)row*EC + e]);
        #pragma unroll
        for (int h=0;h<HHC;h++) s[h] = fmaf(xv, wst[h*EC+e], s[h]);
    }
    #pragma unroll
    for (int h=0;h<HHC;h++){
        #pragma unroll
        for (int off=16; off>=1; off>>=1) s[h] += __shfl_xor_sync(0xffffffffu, s[h], off);
    }
    #pragma unroll
    for (int h=0;h<HHC;h++)
        if (lane == h) dtr[(size_t)row*HHC + h] = s[h];
}

// ---------------- dt path: softplus, r, cumsum (precise exp) ----------------
__global__ void k_dtscan(const float* __restrict__ dtr, const float* __restrict__ dt_bias,
                         const float* __restrict__ A_log,
                         float* __restrict__ dtb, float* __restrict__ rb, float* __restrict__ cumb){
    int k = blockIdx.x / HHC, h = blockIdx.x % HHC;
    __shared__ float part[256];
    float expA = expf(A_log[h]);
    float bias = dt_bias[h];
    int tid = threadIdx.x;
    int tbase = tid*9;
    float loc[9]; float s = 0.f;
    #pragma unroll
    for (int i=0;i<9;i++){
        size_t row = (size_t)k*LSEQ + tbase + i;
        float v  = dtr[row*HHC + h] + bias;
        float dt = (v > 20.f) ? v : log1pf(expf(v));
        dtb[row*HHC+h] = 0.5f*dt;
        rb [row*HHC+h] = expf(-dt*expA);
        s += dt; loc[i] = s;
    }
    part[tid] = s; __syncthreads();
    for (int off=1; off<256; off<<=1){
        float add = (tid >= off) ? part[tid-off] : 0.f;
        __syncthreads();
        part[tid] += add;
        __syncthreads();
    }
    float offset = part[tid] - s;
    #pragma unroll
    for (int i=0;i<9;i++){
        size_t row = (size_t)k*LSEQ + tbase + i;
        cumb[row*HHC+h] = loc[i] + offset;
    }
}

// ---------------- rms(B/C) + rotary: warp per row, deduplicated sincos ----------------
__global__ __launch_bounds__(256) void k_rot(const float* __restrict__ bcb, const float* __restrict__ bias_bc,
                                             const float* __restrict__ theta, const float* __restrict__ cumb,
                                             float* __restrict__ Bt, float* __restrict__ Ct){
    int row  = (blockIdx.x*blockDim.x + threadIdx.x) >> 5;
    int lane = threadIdx.x & 31;
    if (row >= ROWS) return;
    float bc = bcb[(size_t)row*32 + lane] + bias_bc[lane];
    float s = bc*bc;
    s += __shfl_xor_sync(0xffffffffu, s, 1);
    s += __shfl_xor_sync(0xffffffffu, s, 2);
    s += __shfl_xor_sync(0xffffffffu, s, 4);
    s += __shfl_xor_sync(0xffffffffu, s, 8);
    float rn = rsqrtf(s*(1.f/16.f) + 1e-6f);
    float v = bc * rn;

    float cval = (lane < HHC) ? cumb[(size_t)row*HHC + lane] : 0.f;
    float th0 = theta[lane];
    float th1 = (lane < 16) ? theta[32 + lane] : 0.f;
    float cd0 = __shfl_sync(0xffffffffu, cval, lane>>3);
    float cd1 = __shfl_sync(0xffffffffu, cval, 4 + (lane>>3));
    float s0, c0, s1, c1;
    sincosf(cd0*th0, &s0, &c0);
    sincosf(cd1*th1, &s1, &c1);

    int j = lane & 15;
    int half = lane & 16;
    int i = j >> 1;
    float v0 = __shfl_sync(0xffffffffu, v, half + 2*i);
    float v1 = __shfl_sync(0xffffffffu, v, half + 2*i + 1);
    bool odd = (j & 1) != 0;
    #pragma unroll
    for (int h=0; h<HHC; h++){
        int p = h*8 + i;
        float cc = (h < 4) ? __shfl_sync(0xffffffffu, c0, p)
                           : __shfl_sync(0xffffffffu, c1, p - 32);
        float ss = (h < 4) ? __shfl_sync(0xffffffffu, s0, p)
                           : __shfl_sync(0xffffffffu, s1, p - 32);
        float o = odd ? fmaf(-v0, ss, v1*cc) : fmaf(v0, cc, v1*ss);
        float* dst = half ? Ct : Bt;
        dst[((size_t)row*HHC + h)*16 + j] = o;
    }
}

// ---------------- scan phase A: per-segment local scan (h_in = 0) ----------------
#define SCH 32
__global__ __launch_bounds__(256) void k_scanA(const float* __restrict__ Bt, const float* __restrict__ Ct,
                                               const float* __restrict__ xh, const float* __restrict__ dtb,
                                               const float* __restrict__ rb, const float* __restrict__ Dsk,
                                               float* __restrict__ y, float* __restrict__ rc,
                                               float* __restrict__ hend){
    __shared__ __align__(16) float Bs[2][SCH][16];
    __shared__ __align__(16) float Cs[2][SCH][16];
    __shared__ __align__(16) float Xs[2][SCH][64];
    __shared__ float Ds[2][SCH];
    __shared__ float Rs[2][SCH];
    __shared__ __align__(16) float Ys[SCH][64];
    __shared__ float Rys[SCH];

    int kh = blockIdx.x; int k = kh/HHC, h = kh%HHC;
    int seg = blockIdx.y;
    int tseg0 = seg*TSEG;
    int tid = threadIdx.x;
    int p = tid>>2, ng = tid&3;
    size_t bBase = ((size_t)k*LSEQ*HHC + h)*16;
    size_t xBase = (size_t)k*LSEQ*EC + (size_t)h*64;
    size_t sBase = (size_t)k*LSEQ*HHC + h;
    float dsk = Dsk[h];
    float* ybase = y + (size_t)k*LSEQ*EC + h*64;
    size_t rcBase = (size_t)kh*LSEQ;

    auto stage = [&](int buf, int t0){
        {
            int id = tid & 127;
            int tl = id>>2, sg = id&3;
            size_t off = bBase + (size_t)(t0+tl)*96 + sg*4;
            if (tid < 128){
                uint32_t d = (uint32_t)__cvta_generic_to_shared(&Bs[buf][tl][sg*4]);
                CP16(d, &Bt[off]);
            } else {
                uint32_t d = (uint32_t)__cvta_generic_to_shared(&Cs[buf][tl][sg*4]);
                CP16(d, &Ct[off]);
            }
        }
        #pragma unroll
        for (int j=0;j<2;j++){
            int i = tid + j*256;
            int tl = i>>4, c = i&15;
            uint32_t d = (uint32_t)__cvta_generic_to_shared(&Xs[buf][tl][c*4]);
            CP16(d, &xh[xBase + (size_t)(t0+tl)*EC + c*4]);
        }
        if (tid < SCH){
            uint32_t d = (uint32_t)__cvta_generic_to_shared(&Ds[buf][tid]);
            CP4(d, &dtb[sBase + (size_t)(t0+tid)*HHC]);
        } else if (tid < 2*SCH){
            int tl = tid - SCH;
            uint32_t d = (uint32_t)__cvta_generic_to_shared(&Rs[buf][tl]);
            CP4(d, &rb[sBase + (size_t)(t0+tl)*HHC]);
        }
        CPCOMMIT();
    };

    float hs0=0.f,hs1=0.f,hs2=0.f,hs3=0.f;
    float bx0=0.f,bx1=0.f,bx2=0.f,bx3=0.f;
    if (seg > 0){
        int tp = tseg0 - 1;
        float4 Bp = *(const float4*)&Bt[bBase + (size_t)tp*96 + ng*4];
        float xp = xh[xBase + (size_t)tp*EC + p];
        bx0 = Bp.x*xp; bx1 = Bp.y*xp; bx2 = Bp.z*xp; bx3 = Bp.w*xp;
    }
    float rp = 1.f;

    stage(0, tseg0);
    const int NCHUNK = TSEG/SCH;   // 9
    for (int c=0; c<NCHUNK; ++c){
        int buf = c&1;
        if (c+1 < NCHUNK) stage(buf^1, tseg0 + (c+1)*SCH);
        else CPCOMMIT();
        CPWAIT1();
        __syncthreads();

        #pragma unroll 4
        for (int t=0; t<SCH; ++t){
            float4 Bv = *(const float4*)&Bs[buf][t][ng*4];
            float4 Cv = *(const float4*)&Cs[buf][t][ng*4];
            float xv = Xs[buf][t][p];
            float ad = Ds[buf][t];
            float rv = Rs[buf][t];
            float G0 = Bv.x*xv, G1 = Bv.y*xv, G2 = Bv.z*xv, G3 = Bv.w*xv;
            float u0 = fmaf(rv,bx0,G0), u1 = fmaf(rv,bx1,G1);
            float u2 = fmaf(rv,bx2,G2), u3 = fmaf(rv,bx3,G3);
            hs0 = fmaf(rv,hs0,ad*u0); hs1 = fmaf(rv,hs1,ad*u1);
            hs2 = fmaf(rv,hs2,ad*u2); hs3 = fmaf(rv,hs3,ad*u3);
            bx0=G0; bx1=G1; bx2=G2; bx3=G3;
            rp *= rv;
            float v = fmaf(Cv.x,hs0, fmaf(Cv.y,hs1, fmaf(Cv.z,hs2, Cv.w*hs3)));
            v += __shfl_xor_sync(0xffffffffu, v, 1);
            v += __shfl_xor_sync(0xffffffffu, v, 2);
            if (ng == 0) Ys[t][p] = fmaf(dsk, xv, v);
            if (tid == 0) Rys[t] = rp;
        }
        __syncthreads();
        int t0 = tseg0 + c*SCH;
        #pragma unroll
        for (int j=0;j<2;j++){
            int i = tid + j*256;
            int tl = i>>4, cc = i&15;
            *(float4*)&ybase[(size_t)(t0+tl)*EC + cc*4] = *(const float4*)&Ys[tl][cc*4];
        }
        if (tid < SCH) rc[rcBase + t0 + tid] = Rys[tid];
    }
    float4 he = make_float4(hs0,hs1,hs2,hs3);
    *(float4*)&hend[(((size_t)kh*NSEG + seg)*PC + p)*NC + ng*4] = he;
}

// ---------------- scan phase B: sequential combine of segment boundary states ----------------
__global__ __launch_bounds__(256) void k_scanB(const float* __restrict__ hend,
                                               const float* __restrict__ rc,
                                               float* __restrict__ hin){
    int kh = blockIdx.x;
    int tid = threadIdx.x;
    int p = tid>>2, ng = tid&3;
    float4 hi = make_float4(0.f,0.f,0.f,0.f);
    #pragma unroll
    for (int s=0; s<NSEG; ++s){
        size_t idx = (((size_t)kh*NSEG + s)*PC + p)*NC + ng*4;
        *(float4*)&hin[idx] = hi;
        float4 he = *(const float4*)&hend[idx];
        float Rseg = rc[(size_t)kh*LSEQ + s*TSEG + TSEG-1];
        hi.x = fmaf(Rseg, hi.x, he.x);
        hi.y = fmaf(Rseg, hi.y, he.y);
        hi.z = fmaf(Rseg, hi.z, he.z);
        hi.w = fmaf(Rseg, hi.w, he.w);
    }
}

// ---------------- scan phase C: fixup y += R(t) * (C_t · h_in) ----------------
__global__ __launch_bounds__(256) void k_scanC(const float* __restrict__ Ct,
                                               const float* __restrict__ rc,
                                               const float* __restrict__ hin,
                                               float* __restrict__ y){
    int seg = blockIdx.y;
    if (seg == 0) return;
    __shared__ float Hs[PC][NC+1];
    __shared__ float Cs[SCH][NC+1];
    __shared__ float Rsh[SCH];
    int kh = blockIdx.x; int k = kh/HHC, h = kh%HHC;
    int tid = threadIdx.x;
    int p = tid&63, tq = tid>>6;
    size_t hBase = ((size_t)kh*NSEG + seg)*PC*NC;
    for (int i=tid; i<PC*NC; i+=256) Hs[i>>4][i&15] = hin[hBase + i];
    __syncthreads();
    float hn[NC];
    #pragma unroll
    for (int i=0;i<NC;i++) hn[i] = Hs[p][i];

    size_t bBase = ((size_t)k*LSEQ*HHC + h)*16;
    size_t rcBase = (size_t)kh*LSEQ;
    float* ybase = y + (size_t)k*LSEQ*EC + h*64;
    int tseg0 = seg*TSEG;

    for (int c=0; c<TSEG/SCH; ++c){
        int t0 = tseg0 + c*SCH;
        for (int i=tid; i<SCH*NC; i+=256){
            int tl = i>>4, nn = i&15;
            Cs[tl][nn] = Ct[bBase + (size_t)(t0+tl)*96 + nn];
        }
        if (tid < SCH) Rsh[tid] = rc[rcBase + t0 + tid];
        __syncthreads();
        if (Rsh[0] == 0.f) break;
        #pragma unroll
        for (int jt=0; jt<SCH/4; ++jt){
            int tl = tq + jt*4;
            float R = Rsh[tl];
            if (R != 0.f){
                float corr = 0.f;
                #pragma unroll
                for (int i=0;i<NC;i++) corr = fmaf(Cs[tl][i], hn[i], corr);
                ybase[(size_t)(t0+tl)*EC + p] += R*corr;
            }
        }
        __syncthreads();
    }
}

// ---------------- g = tf32(rms(y * silu(z)) * rms_w)  (warp per row, compact z) ----------------
__global__ void k_gate(const float* __restrict__ y, const float* __restrict__ z,
                       const float* __restrict__ rms_w, float* __restrict__ g){
    int warp = (blockIdx.x*blockDim.x + threadIdx.x) >> 5;
    int lane = threadIdx.x & 31;
    if (warp >= ROWS) return;
    size_t base = (size_t)warp*EC;
    float v[12]; float s2 = 0.f;
    #pragma unroll
    for (int j=0;j<12;j++){
        int e = lane + j*32;
        float t = y[base + e] * siluf(z[base + e]);
        v[j] = t; s2 += t*t;
    }
    #pragma unroll
    for (int off=16; off>=1; off>>=1) s2 += __shfl_xor_sync(0xffffffffu, s2, off);
    float rn = rsqrtf(s2*(1.f/384.f) + 1e-6f);
    #pragma unroll
    for (int j=0;j<12;j++){
        int e = lane + j*32;
        g[base + e] = f2tf32f(v[j]*rn*rms_w[e]);
    }
}

// ---------------- merge 4 dirs of moG -> mT (tf32) ----------------
__global__ void k_xmerge(const float* __restrict__ moG, float* __restrict__ mT){
    int idx = blockIdx.x*blockDim.x + threadIdx.x;
    if (idx >= LSEQ*EC) return;
    int l = idx / EC, e = idx % EC;
    int lt = (l%48)*48 + l/48;
    size_t r0 = (size_t)l*EC + e;
    size_t r1 = (size_t)(LSEQ + lt)*EC + e;
    size_t r2 = (size_t)(2*LSEQ + 2303 - l)*EC + e;
    size_t r3 = (size_t)(3*LSEQ + 2303 - lt)*EC + e;
    mT[idx] = f2tf32f(moG[r0] + moG[r1] + moG[r2] + moG[r3]);
}

// ---------------- LayerNorm + residual ----------------
__global__ void k_ln(const float* __restrict__ pre, const float* __restrict__ x,
                     const float* __restrict__ ln_g, const float* __restrict__ ln_b,
                     const float* __restrict__ res_scale, float* __restrict__ out){
    int warp = (blockIdx.x*blockDim.x + threadIdx.x) >> 5;
    int lane = threadIdx.x & 31;
    if (warp >= LSEQ) return;
    int l = warp;
    float v[6]; float s = 0.f;
    #pragma unroll
    for (int j=0;j<6;j++){ v[j] = pre[(size_t)l*DIMC + lane + j*32]; s += v[j]; }
    #pragma unroll
    for (int off=16; off>=1; off>>=1) s += __shfl_xor_sync(0xffffffffu, s, off);
    float mu = s*(1.f/192.f);
    float q = 0.f;
    #pragma unroll
    for (int j=0;j<6;j++){ float d = v[j]-mu; q += d*d; }
    #pragma unroll
    for (int off=16; off>=1; off>>=1) q += __shfl_xor_sync(0xffffffffu, q, off);
    float inv = rsqrtf(q*(1.f/192.f) + 1e-5f);
    float rs = res_scale[0];
    #pragma unroll
    for (int j=0;j<6;j++){
        int d = lane + j*32;
        out[(size_t)d*LSEQ + l] = x[(size_t)d*LSEQ + l]
            + rs*((v[j]-mu)*inv*ln_g[d] + ln_b[d]);
    }
}

// ---------------- launch ----------------
extern "C" void kernel_launch(void* const* d_in, const int* in_sizes, int n_in,
                              void* d_out, int out_size){
    (void)in_sizes; (void)n_in; (void)out_size;
    const float* x        = (const float*)d_in[0];
    const float* w_in     = (const float*)d_in[1];
    const float* w_zx     = (const float*)d_in[2];
    const float* w_bc     = (const float*)d_in[3];
    const float* bias_bc  = (const float*)d_in[4];
    const float* w_dt     = (const float*)d_in[5];
    const float* dt_bias  = (const float*)d_in[6];
    const float* A_log    = (const float*)d_in[7];
    const float* theta    = (const float*)d_in[8];
    const float* D_skip   = (const float*)d_in[9];
    const float* rms_w    = (const float*)d_in[10];
    const float* w_mout   = (const float*)d_in[11];
    const float* w_out    = (const float*)d_in[12];
    const float* ln_g     = (const float*)d_in[13];
    const float* ln_b     = (const float*)d_in[14];
    const float* resscale = (const float*)d_in[15];
    float* out = (float*)d_out;

    float *b_xseq,*b_projc,*b_gsil,*b_xssmt,*b_wcomb,*b_winT,*b_wmoutT,*b_woutT;
    float *b_z,*b_xh,*b_bcb,*b_dtr,*b_dtb,*b_rb,*b_cum,*b_Bt,*b_Ct,*b_y,*b_g,*b_moG,*b_mT,*b_pre;
    float *b_rc,*b_hend,*b_hin;
    cudaGetSymbolAddress((void**)&b_xseq,  g_xseq);
    cudaGetSymbolAddress((void**)&b_projc, g_projc);
    cudaGetSymbolAddress((void**)&b_gsil,  g_gsil);
    cudaGetSymbolAddress((void**)&b_xssmt, g_xssmt);
    cudaGetSymbolAddress((void**)&b_wcomb, g_wcomb);
    cudaGetSymbolAddress((void**)&b_winT,  g_winT);
    cudaGetSymbolAddress((void**)&b_wmoutT,g_wmoutT);
    cudaGetSymbolAddress((void**)&b_woutT, g_woutT);
    cudaGetSymbolAddress((void**)&b_z,     g_z);
    cudaGetSymbolAddress((void**)&b_xh,    g_xh);
    cudaGetSymbolAddress((void**)&b_bcb,   g_bcb);
    cudaGetSymbolAddress((void**)&b_dtr,   g_dtr);
    cudaGetSymbolAddress((void**)&b_dtb,   g_dtb);
    cudaGetSymbolAddress((void**)&b_rb,    g_rb);
    cudaGetSymbolAddress((void**)&b_cum,   g_cum);
    cudaGetSymbolAddress((void**)&b_Bt,    g_Bt);
    cudaGetSymbolAddress((void**)&b_Ct,    g_Ct);
    cudaGetSymbolAddress((void**)&b_y,     g_y);
    cudaGetSymbolAddress((void**)&b_g,     g_g);
    cudaGetSymbolAddress((void**)&b_moG,   g_moG);
    cudaGetSymbolAddress((void**)&b_mT,    g_mT);
    cudaGetSymbolAddress((void**)&b_pre,   g_pre);
    cudaGetSymbolAddress((void**)&b_rc,    g_rc);
    cudaGetSymbolAddress((void**)&b_hend,  g_hend);
    cudaGetSymbolAddress((void**)&b_hin,   g_hin);

    cudaFuncSetAttribute(k_gemm<0>, cudaFuncAttributeMaxDynamicSharedMemorySize, GEMM_SMEM);
    cudaFuncSetAttribute(k_gemm<1>, cudaFuncAttributeMaxDynamicSharedMemorySize, GEMM_SMEM);
    cudaFuncSetAttribute(k_gemm<2>, cudaFuncAttributeMaxDynamicSharedMemorySize, GEMM_SMEM);
    cudaFuncSetAttribute(k_gemm<3>, cudaFuncAttributeMaxDynamicSharedMemorySize, GEMM_SMEM);

    // 0: fused build + weight prep
    k_prep<<<PREP_BUILD_BLKS + PREP_W_BLKS, 256>>>(x, b_xseq, w_in, w_mout, w_out, w_zx, w_bc,
                                                   b_winT, b_wmoutT, b_woutT, b_wcomb);
    // 1: proj GEMM (9216x768 | K=192); epilogue: projc, xssmt (tf32 silu), gsil
    k_gemm<1><<<dim3(768/128, ROWS/128), 256, GEMM_SMEM>>>(b_xseq, b_winT, b_projc,
                                                           ROWS, 768, DIMC, DIMC,
                                                           b_xssmt, b_gsil, nullptr);
    // fork: dt path (dtgemv->dtscan) on side stream, concurrent with zx GEMM
    cudaEventRecord(g_si.evF, 0);
    cudaStreamWaitEvent(g_si.s, g_si.evF, 0);
    k_dtgemv<<<ROWS/8, 256, 0, g_si.s>>>(b_projc, w_dt, b_dtr);
    k_dtscan<<<KC*HHC, 256, 0, g_si.s>>>(b_dtr, dt_bias, A_log, b_dtb, b_rb, b_cum);
    cudaEventRecord(g_si.evJ, g_si.s);
    // 3: zx GEMM (9216x800 | K=384), split epilogue -> z / xh / bc   (main stream)
    k_gemm<2><<<dim3((ZXW+127)/128, ROWS/128), 256, GEMM_SMEM>>>(b_xssmt, b_wcomb, nullptr,
                                                                 ROWS, ZXW, EC, EC,
                                                                 b_z, b_xh, b_bcb);
    // join before rot (needs cum from side stream + bcb from gemm2)
    cudaStreamWaitEvent(0, g_si.evJ, 0);
    // 5: rms + rotary (deduplicated sincos)
    k_rot<<<ROWS/8, 256>>>(b_bcb, bias_bc, theta, b_cum, b_Bt, b_Ct);
    // 6: split-sequence scan (A local, B combine, C fixup)
    k_scanA<<<dim3(KC*HHC, NSEG), 256>>>(b_Bt, b_Ct, b_xh, b_dtb, b_rb, D_skip, b_y, b_rc, b_hend);
    k_scanB<<<KC*HHC, 256>>>(b_hend, b_rc, b_hin);
    k_scanC<<<dim3(KC*HHC, NSEG), 256>>>(b_Ct, b_rc, b_hin, b_y);
    // 7: gated rms norm
    k_gate<<<(ROWS*32+255)/256, 256>>>(b_y, b_z, rms_w, b_g);
    // 8: mout GEMM (9216x384 | K=384), epilogue multiplies by gsil -> moG
    k_gemm<3><<<dim3(EC/128, ROWS/128), 256, GEMM_SMEM>>>(b_g, b_wmoutT, b_moG,
                                                          ROWS, EC, EC, EC,
                                                          b_gsil, nullptr, nullptr);
    // 9: 4-direction merge
    k_xmerge<<<(LSEQ*EC+255)/256, 256>>>(b_moG, b_mT);
    // 10: output projection GEMM (2304x192 | K=384), single launch
    k_gemm<0><<<dim3((DIMC+127)/128, LSEQ/128), 256, GEMM_SMEM>>>(b_mT, b_woutT, b_pre,
                                                                  LSEQ, DIMC, EC, EC,
                                                                  nullptr, nullptr, nullptr);
    // 11: layernorm + residual
    k_ln<<<(LSEQ*32+255)/256, 256>>>(b_pre, x, ln_g, ln_b, resscale, out);
}

// round 16
// speedup vs baseline: 1.6856x; 1.0764x over previous
#include <cuda_runtime.h>
#include <cstdint>
#include <math.h>

#define LSEQ 2304
#define DIMC 192
#define EC   384
#define NC   16
#define PC   64
#define HHC  6
#define KC   4
#define ROWS (KC*LSEQ)   /* 9216 */
#define ZXW  800         /* zx GEMM logical N: 384 z + 384 xh + 32 bc */
#define NSEG 12
#define TSEG (LSEQ/NSEG) /* 192 */

// ---------------- scratch (static device globals; no allocation) ----------------
static __device__ __align__(16) float g_xseq[ROWS*DIMC];      // tf32-rounded
static __device__ __align__(16) float g_projc[ROWS*EC];       // fp32 pre-silu (ssm half)
static __device__ __align__(16) float g_gsil [ROWS*EC];       // fp32 silu(gate half)
static __device__ __align__(16) float g_xssmt[ROWS*EC];       // tf32 silu(proj) (GEMM epi)
static __device__ __align__(16) float g_wcomb[EC*ZXW];        // tf32-rounded
static __device__ __align__(16) float g_winT[DIMC*768];       // tf32-rounded
static __device__ __align__(16) float g_wmoutT[EC*EC];        // tf32-rounded
static __device__ __align__(16) float g_woutT[EC*DIMC];       // tf32-rounded
static __device__ __align__(16) float g_z  [ROWS*EC];         // fp32 (zx epi split)
static __device__ __align__(16) float g_xh [ROWS*EC];         // fp32
static __device__ __align__(16) float g_bcb[ROWS*32];         // fp32
static __device__ __align__(16) float g_dtr[ROWS*HHC];
static __device__ __align__(16) float g_dtb[ROWS*HHC];        // 0.5*dt
static __device__ __align__(16) float g_rb[ROWS*HHC];
static __device__ __align__(16) float g_cum[ROWS*HHC];
static __device__ __align__(16) float g_Bt[ROWS*HHC*NC];
static __device__ __align__(16) float g_Ct[ROWS*HHC*NC];
static __device__ __align__(16) float g_y[ROWS*EC];
static __device__ __align__(16) float g_g[ROWS*EC];           // tf32-rounded
static __device__ __align__(16) float g_moG[ROWS*EC];         // mout * gsil (EPI 3)
static __device__ __align__(16) float g_mT[LSEQ*EC];          // tf32-rounded
static __device__ __align__(16) float g_pre[LSEQ*DIMC];
static __device__ __align__(16) float g_rc[KC*HHC*LSEQ];
static __device__ __align__(16) float g_hend[KC*HHC*NSEG*PC*NC];
static __device__ __align__(16) float g_hin[KC*HHC*NSEG*PC*NC];

// ---------------- side stream + fork/join events (created at load; no dev mem) ----
struct StreamInit {
    cudaStream_t s; cudaEvent_t evF0, evF, evJ, evP;
    StreamInit(){
        cudaStreamCreateWithFlags(&s, cudaStreamNonBlocking);
        cudaEventCreateWithFlags(&evF0, cudaEventDisableTiming);
        cudaEventCreateWithFlags(&evF,  cudaEventDisableTiming);
        cudaEventCreateWithFlags(&evJ,  cudaEventDisableTiming);
        cudaEventCreateWithFlags(&evP,  cudaEventDisableTiming);
    }
};
static StreamInit g_si;

__device__ __forceinline__ float siluf(float v){
    return __fdividef(v, 1.f + __expf(-v));
}
__device__ __forceinline__ float f2tf32f(float f){
    uint32_t u; asm("cvt.rna.tf32.f32 %0, %1;" : "=r"(u) : "f"(f));
    return __uint_as_float(u);
}
__device__ __forceinline__ void ldsm_x4(uint32_t &r0, uint32_t &r1, uint32_t &r2, uint32_t &r3,
                                        uint32_t addr){
    asm volatile("ldmatrix.sync.aligned.m8n8.x4.shared.b16 {%0,%1,%2,%3}, [%4];"
                 : "=r"(r0), "=r"(r1), "=r"(r2), "=r"(r3) : "r"(addr));
}

#define CP16(dst,src) asm volatile("cp.async.cg.shared.global [%0],[%1],16;\n"::"r"(dst),"l"(src))
#define CP16Z(dst,src) asm volatile("cp.async.cg.shared.global [%0],[%1],16,0;\n"::"r"(dst),"l"(src))
#define CP4(dst,src)  asm volatile("cp.async.ca.shared.global [%0],[%1],4;\n"::"r"(dst),"l"(src))
#define CPCOMMIT()    asm volatile("cp.async.commit_group;\n")
#define CPWAIT1()     asm volatile("cp.async.wait_group 1;\n")

// ---------------- prep A: build 4-dir sequence + winT (needed by gemm1) ----------------
#define WPA (DIMC*768)
#define PREP_BUILD_BLKS (DIMC*KC)   /* 768 */
#define PREPA_W_BLKS ((WPA+255)/256)
__global__ __launch_bounds__(256) void k_prepA(const float* __restrict__ x, float* __restrict__ xseq,
                        const float* __restrict__ w_in, float* __restrict__ winT){
    int tid = threadIdx.x;
    if (blockIdx.x < PREP_BUILD_BLKS){
        __shared__ float sm[LSEQ + LSEQ/48];
        int d = blockIdx.x >> 2;
        int k = blockIdx.x & 3;
        for (int i = tid; i < LSEQ; i += 256)
            sm[i + i/48] = x[d*LSEQ + i];
        __syncthreads();
        size_t obase = (size_t)k*(LSEQ*DIMC) + (size_t)d*LSEQ;
        for (int l = tid; l < LSEQ; l += 256){
            int m;
            if      (k==0) m = l;
            else if (k==1) m = (l%48)*48 + l/48;
            else if (k==2) m = 2303 - l;
            else { int lr = 2303-l; m = (lr%48)*48 + lr/48; }
            xseq[obase + l] = f2tf32f(sm[m + m/48]);
        }
        return;
    }
    int idx = (blockIdx.x - PREP_BUILD_BLKS)*256 + tid;
    if (idx < WPA) winT[idx] = f2tf32f(w_in[idx]);
}

// ---------------- prep B (side stream): wcomb + wmoutT + woutT ----------------
#define WB1 (EC*EC)
#define WB2 (WB1 + EC*DIMC)
#define WB3 (WB2 + EC*ZXW)
__global__ __launch_bounds__(256) void k_prepB(const float* __restrict__ w_mout,
                        const float* __restrict__ w_out, const float* __restrict__ wzx,
                        const float* __restrict__ wbc,
                        float* __restrict__ wmoutT, float* __restrict__ woutT,
                        float* __restrict__ wcomb){
    int idx = blockIdx.x*256 + threadIdx.x;
    if (idx >= WB3) return;
    if (idx < WB1){ wmoutT[idx] = f2tf32f(w_mout[idx]); return; }
    if (idx < WB2){ int i = idx-WB1; woutT[i] = f2tf32f(w_out[i]); return; }
    int i = idx-WB2;
    int kk = i / ZXW, j = i % ZXW;
    float v = (j < 768) ? wzx[kk*768 + j] : wbc[kk*32 + (j-768)];
    wcomb[i] = f2tf32f(v);
}

// ---------------- tf32 tensor-core GEMM, BK=32, 3-stage cp.async, 1 sync/k-tile ----------------
#define GEMM_SMEM ((3*128*36 + 3*32*136)*4)
#define AS(b,r,c) Asp[(b)*128*36 + (r)*36 + (c)]
#define BS(b,r,c) Bsp[(b)*32*136 + (r)*136 + (c)]
template<int EPI>
__global__ __launch_bounds__(256,2) void k_gemm(const float* __restrict__ A,
                                                const float* __restrict__ B,
                                                float* __restrict__ C,
                                                int M, int N, int LDA, int KLEN,
                                                float* __restrict__ o1,
                                                float* __restrict__ o2,
                                                float* __restrict__ o3){
    extern __shared__ float dynsmem[];
    float* Asp = dynsmem;
    float* Bsp = dynsmem + 3*128*36;
    const int BM=128, BN=128, BK=32;
    int tid  = threadIdx.x;
    int warp = tid>>5, lane = tid&31;
    int wm = warp>>2, wn = warp&3;
    int gid = lane>>2, tig = lane&3;
    int bm = blockIdx.y*BM, bn = blockIdx.x*BN;
    bool wActive = (bn + wn*32) < N;   // uniform per warp

    int q = lane>>3, rl = lane&7;
    uint32_t aAddrBase = (uint32_t)__cvta_generic_to_shared(Asp)
        + (uint32_t)((((q&1)*8 + rl)*36 + (q>>1)*4) * 4)
        + (uint32_t)(wm*64*36*4);

    float acc[4][4][4];
    #pragma unroll
    for (int m=0;m<4;m++)
        #pragma unroll
        for (int n=0;n<4;n++)
            #pragma unroll
            for (int i=0;i<4;i++) acc[m][n][i]=0.f;

    auto stage = [&](int buf, int k0){
        #pragma unroll
        for (int j=0;j<4;j++){
            int i = tid + j*256;
            int r = i>>3, kc = i&7;
            uint32_t dst = (uint32_t)__cvta_generic_to_shared(&AS(buf, r, kc*4));
            CP16(dst, &A[(size_t)(bm+r)*LDA + k0 + kc*4]);
        }
        #pragma unroll
        for (int j=0;j<4;j++){
            int i = tid + j*256;
            int r = i>>5, c = i&31;
            uint32_t dst = (uint32_t)__cvta_generic_to_shared(&BS(buf, r, c*4));
            if (bn + c*4 + 4 <= N) CP16(dst, &B[(size_t)(k0+r)*N + bn + c*4]);
            else                   CP16Z(dst, B);
        }
        CPCOMMIT();
    };

    int nk = KLEN/BK;
    stage(0, 0);
    stage(1, BK);
    for (int kt=0; kt<nk; ++kt){
        CPWAIT1();
        __syncthreads();
        if (kt+2 < nk) stage((kt+2)%3, (kt+2)*BK);
        else CPCOMMIT();
        int buf = kt - (kt/3)*3;

        if (wActive){
            uint32_t aBufBase = aAddrBase + (uint32_t)(buf*128*36*4);
            #pragma unroll
            for (int kk=0; kk<4; kk++){
                int kb = kk*8;
                uint32_t a[4][4];
                #pragma unroll
                for (int m=0;m<4;m++){
                    ldsm_x4(a[m][0], a[m][1], a[m][2], a[m][3],
                            aBufBase + (uint32_t)((m*16*36 + kb)*4));
                }
                uint32_t b[4][2];
                #pragma unroll
                for (int n=0;n<4;n++){
                    int nc = wn*32 + n*8;
                    b[n][0] = __float_as_uint(BS(buf, kb+tig,   nc+gid));
                    b[n][1] = __float_as_uint(BS(buf, kb+tig+4, nc+gid));
                }
                #pragma unroll
                for (int m=0;m<4;m++)
                    #pragma unroll
                    for (int n=0;n<4;n++){
                        asm volatile(
                            "mma.sync.aligned.m16n8k8.row.col.f32.tf32.tf32.f32 "
                            "{%0,%1,%2,%3}, {%4,%5,%6,%7}, {%8,%9}, {%0,%1,%2,%3};"
                            : "+f"(acc[m][n][0]), "+f"(acc[m][n][1]),
                              "+f"(acc[m][n][2]), "+f"(acc[m][n][3])
                            : "r"(a[m][0]), "r"(a[m][1]), "r"(a[m][2]), "r"(a[m][3]),
                              "r"(b[n][0]), "r"(b[n][1]));
                    }
            }
        }
    }
    if (!wActive) return;
    #pragma unroll
    for (int m=0;m<4;m++){
        int row0 = bm + wm*64 + m*16 + gid;
        #pragma unroll
        for (int n=0;n<4;n++){
            int col = bn + wn*32 + n*8 + tig*2;
            #pragma unroll
            for (int cc=0; cc<2; cc++){
                int cl = col + cc;
                if (cl >= N) continue;
                float v0 = acc[m][n][cc];
                float v1 = acc[m][n][2+cc];
                if (EPI == 0){
                    C[(size_t)row0*N + cl] = v0;
                    C[(size_t)(row0+8)*N + cl] = v1;
                } else if (EPI == 1){
                    if (cl < 384){
                        C[(size_t)row0*EC + cl] = v0;
                        C[(size_t)(row0+8)*EC + cl] = v1;
                        o1[(size_t)row0*EC + cl] = f2tf32f(siluf(v0));
                        o1[(size_t)(row0+8)*EC + cl] = f2tf32f(siluf(v1));
                    } else {
                        o2[(size_t)row0*EC + cl-384] = siluf(v0);
                        o2[(size_t)(row0+8)*EC + cl-384] = siluf(v1);
                    }
                } else if (EPI == 2){
                    if (cl < 384){
                        o1[(size_t)row0*EC + cl] = v0;
                        o1[(size_t)(row0+8)*EC + cl] = v1;
                    } else if (cl < 768){
                        o2[(size_t)row0*EC + cl-384] = v0;
                        o2[(size_t)(row0+8)*EC + cl-384] = v1;
                    } else {
                        o3[(size_t)row0*32 + cl-768] = v0;
                        o3[(size_t)(row0+8)*32 + cl-768] = v1;
                    }
                } else {  // EPI == 3: C = acc * o1 (gate silu)
                    C[(size_t)row0*N + cl] = v0 * o1[(size_t)row0*EC + cl];
                    C[(size_t)(row0+8)*N + cl] = v1 * o1[(size_t)(row0+8)*EC + cl];
                }
            }
        }
    }
}

// ---------------- dt GEMV ----------------
__global__ __launch_bounds__(256) void k_dtgemv(const float* __restrict__ projc,
                                                const float* __restrict__ w_dt,
                                                float* __restrict__ dtr){
    __shared__ float wst[HHC*EC];
    int tid = threadIdx.x;
    for (int i=tid; i<EC*HHC; i+=256){
        int h = i % HHC, e = i / HHC;
        wst[h*EC + e] = w_dt[i];
    }
    __syncthreads();
    int warp = tid>>5, lane = tid&31;
    int row = blockIdx.x*8 + warp;
    float s[HHC];
    #pragma unroll
    for (int h=0;h<HHC;h++) s[h]=0.f;
    #pragma unroll
    for (int j=0;j<12;j++){
        int e = lane + j*32;
        float xv = siluf(projc[(size_t)row*EC + e]);
        #pragma unroll
        for (int h=0;h<HHC;h++) s[h] = fmaf(xv, wst[h*EC+e], s[h]);
    }
    #pragma unroll
    for (int h=0;h<HHC;h++){
        #pragma unroll
        for (int off=16; off>=1; off>>=1) s[h] += __shfl_xor_sync(0xffffffffu, s[h], off);
    }
    #pragma unroll
    for (int h=0;h<HHC;h++)
        if (lane == h) dtr[(size_t)row*HHC + h] = s[h];
}

// ---------------- dt path: softplus, r, cumsum (precise exp) ----------------
__global__ void k_dtscan(const float* __restrict__ dtr, const float* __restrict__ dt_bias,
                         const float* __restrict__ A_log,
                         float* __restrict__ dtb, float* __restrict__ rb, float* __restrict__ cumb){
    int k = blockIdx.x / HHC, h = blockIdx.x % HHC;
    __shared__ float part[256];
    float expA = expf(A_log[h]);
    float bias = dt_bias[h];
    int tid = threadIdx.x;
    int tbase = tid*9;
    float loc[9]; float s = 0.f;
    #pragma unroll
    for (int i=0;i<9;i++){
        size_t row = (size_t)k*LSEQ + tbase + i;
        float v  = dtr[row*HHC + h] + bias;
        float dt = (v > 20.f) ? v : log1pf(expf(v));
        dtb[row*HHC+h] = 0.5f*dt;
        rb [row*HHC+h] = expf(-dt*expA);
        s += dt; loc[i] = s;
    }
    part[tid] = s; __syncthreads();
    for (int off=1; off<256; off<<=1){
        float add = (tid >= off) ? part[tid-off] : 0.f;
        __syncthreads();
        part[tid] += add;
        __syncthreads();
    }
    float offset = part[tid] - s;
    #pragma unroll
    for (int i=0;i<9;i++){
        size_t row = (size_t)k*LSEQ + tbase + i;
        cumb[row*HHC+h] = loc[i] + offset;
    }
}

// ---------------- rms(B/C) + rotary: warp per row, deduplicated sincos ----------------
__global__ __launch_bounds__(256) void k_rot(const float* __restrict__ bcb, const float* __restrict__ bias_bc,
                                             const float* __restrict__ theta, const float* __restrict__ cumb,
                                             float* __restrict__ Bt, float* __restrict__ Ct){
    int row  = (blockIdx.x*blockDim.x + threadIdx.x) >> 5;
    int lane = threadIdx.x & 31;
    if (row >= ROWS) return;
    float bc = bcb[(size_t)row*32 + lane] + bias_bc[lane];
    float s = bc*bc;
    s += __shfl_xor_sync(0xffffffffu, s, 1);
    s += __shfl_xor_sync(0xffffffffu, s, 2);
    s += __shfl_xor_sync(0xffffffffu, s, 4);
    s += __shfl_xor_sync(0xffffffffu, s, 8);
    float rn = rsqrtf(s*(1.f/16.f) + 1e-6f);
    float v = bc * rn;

    float cval = (lane < HHC) ? cumb[(size_t)row*HHC + lane] : 0.f;
    float th0 = theta[lane];
    float th1 = (lane < 16) ? theta[32 + lane] : 0.f;
    float cd0 = __shfl_sync(0xffffffffu, cval, lane>>3);
    float cd1 = __shfl_sync(0xffffffffu, cval, 4 + (lane>>3));
    float s0, c0, s1, c1;
    sincosf(cd0*th0, &s0, &c0);
    sincosf(cd1*th1, &s1, &c1);

    int j = lane & 15;
    int half = lane & 16;
    int i = j >> 1;
    float v0 = __shfl_sync(0xffffffffu, v, half + 2*i);
    float v1 = __shfl_sync(0xffffffffu, v, half + 2*i + 1);
    bool odd = (j & 1) != 0;
    #pragma unroll
    for (int h=0; h<HHC; h++){
        int p = h*8 + i;
        float cc = (h < 4) ? __shfl_sync(0xffffffffu, c0, p)
                           : __shfl_sync(0xffffffffu, c1, p - 32);
        float ss = (h < 4) ? __shfl_sync(0xffffffffu, s0, p)
                           : __shfl_sync(0xffffffffu, s1, p - 32);
        float o = odd ? fmaf(-v0, ss, v1*cc) : fmaf(v0, cc, v1*ss);
        float* dst = half ? Ct : Bt;
        dst[((size_t)row*HHC + h)*16 + j] = o;
    }
}

// ---------------- scan phase A: per-segment local scan (h_in = 0) ----------------
#define SCH 32
__global__ __launch_bounds__(256) void k_scanA(const float* __restrict__ Bt, const float* __restrict__ Ct,
                                               const float* __restrict__ xh, const float* __restrict__ dtb,
                                               const float* __restrict__ rb, const float* __restrict__ Dsk,
                                               float* __restrict__ y, float* __restrict__ rc,
                                               float* __restrict__ hend){
    __shared__ __align__(16) float Bs[2][SCH][16];
    __shared__ __align__(16) float Cs[2][SCH][16];
    __shared__ __align__(16) float Xs[2][SCH][64];
    __shared__ float Ds[2][SCH];
    __shared__ float Rs[2][SCH];
    __shared__ __align__(16) float Ys[SCH][64];
    __shared__ float Rys[SCH];

    int kh = blockIdx.x; int k = kh/HHC, h = kh%HHC;
    int seg = blockIdx.y;
    int tseg0 = seg*TSEG;
    int tid = threadIdx.x;
    int p = tid>>2, ng = tid&3;
    size_t bBase = ((size_t)k*LSEQ*HHC + h)*16;
    size_t xBase = (size_t)k*LSEQ*EC + (size_t)h*64;
    size_t sBase = (size_t)k*LSEQ*HHC + h;
    float dsk = Dsk[h];
    float* ybase = y + (size_t)k*LSEQ*EC + h*64;
    size_t rcBase = (size_t)kh*LSEQ;

    auto stage = [&](int buf, int t0){
        {
            int id = tid & 127;
            int tl = id>>2, sg = id&3;
            size_t off = bBase + (size_t)(t0+tl)*96 + sg*4;
            if (tid < 128){
                uint32_t d = (uint32_t)__cvta_generic_to_shared(&Bs[buf][tl][sg*4]);
                CP16(d, &Bt[off]);
            } else {
                uint32_t d = (uint32_t)__cvta_generic_to_shared(&Cs[buf][tl][sg*4]);
                CP16(d, &Ct[off]);
            }
        }
        #pragma unroll
        for (int j=0;j<2;j++){
            int i = tid + j*256;
            int tl = i>>4, c = i&15;
            uint32_t d = (uint32_t)__cvta_generic_to_shared(&Xs[buf][tl][c*4]);
            CP16(d, &xh[xBase + (size_t)(t0+tl)*EC + c*4]);
        }
        if (tid < SCH){
            uint32_t d = (uint32_t)__cvta_generic_to_shared(&Ds[buf][tid]);
            CP4(d, &dtb[sBase + (size_t)(t0+tid)*HHC]);
        } else if (tid < 2*SCH){
            int tl = tid - SCH;
            uint32_t d = (uint32_t)__cvta_generic_to_shared(&Rs[buf][tl]);
            CP4(d, &rb[sBase + (size_t)(t0+tl)*HHC]);
        }
        CPCOMMIT();
    };

    float hs0=0.f,hs1=0.f,hs2=0.f,hs3=0.f;
    float bx0=0.f,bx1=0.f,bx2=0.f,bx3=0.f;
    if (seg > 0){
        int tp = tseg0 - 1;
        float4 Bp = *(const float4*)&Bt[bBase + (size_t)tp*96 + ng*4];
        float xp = xh[xBase + (size_t)tp*EC + p];
        bx0 = Bp.x*xp; bx1 = Bp.y*xp; bx2 = Bp.z*xp; bx3 = Bp.w*xp;
    }
    float rp = 1.f;

    stage(0, tseg0);
    const int NCHUNK = TSEG/SCH;   // 6
    for (int c=0; c<NCHUNK; ++c){
        int buf = c&1;
        if (c+1 < NCHUNK) stage(buf^1, tseg0 + (c+1)*SCH);
        else CPCOMMIT();
        CPWAIT1();
        __syncthreads();

        #pragma unroll 4
        for (int t=0; t<SCH; ++t){
            float4 Bv = *(const float4*)&Bs[buf][t][ng*4];
            float4 Cv = *(const float4*)&Cs[buf][t][ng*4];
            float xv = Xs[buf][t][p];
            float ad = Ds[buf][t];
            float rv = Rs[buf][t];
            float G0 = Bv.x*xv, G1 = Bv.y*xv, G2 = Bv.z*xv, G3 = Bv.w*xv;
            float u0 = fmaf(rv,bx0,G0), u1 = fmaf(rv,bx1,G1);
            float u2 = fmaf(rv,bx2,G2), u3 = fmaf(rv,bx3,G3);
            hs0 = fmaf(rv,hs0,ad*u0); hs1 = fmaf(rv,hs1,ad*u1);
            hs2 = fmaf(rv,hs2,ad*u2); hs3 = fmaf(rv,hs3,ad*u3);
            bx0=G0; bx1=G1; bx2=G2; bx3=G3;
            rp *= rv;
            float v = fmaf(Cv.x,hs0, fmaf(Cv.y,hs1, fmaf(Cv.z,hs2, Cv.w*hs3)));
            v += __shfl_xor_sync(0xffffffffu, v, 1);
            v += __shfl_xor_sync(0xffffffffu, v, 2);
            if (ng == 0) Ys[t][p] = fmaf(dsk, xv, v);
            if (tid == 0) Rys[t] = rp;
        }
        __syncthreads();
        int t0 = tseg0 + c*SCH;
        #pragma unroll
        for (int j=0;j<2;j++){
            int i = tid + j*256;
            int tl = i>>4, cc = i&15;
            *(float4*)&ybase[(size_t)(t0+tl)*EC + cc*4] = *(const float4*)&Ys[tl][cc*4];
        }
        if (tid < SCH) rc[rcBase + t0 + tid] = Rys[tid];
    }
    float4 he = make_float4(hs0,hs1,hs2,hs3);
    *(float4*)&hend[(((size_t)kh*NSEG + seg)*PC + p)*NC + ng*4] = he;
}

// ---------------- scan phase B: sequential combine of segment boundary states ----------------
__global__ __launch_bounds__(256) void k_scanB(const float* __restrict__ hend,
                                               const float* __restrict__ rc,
                                               float* __restrict__ hin){
    int kh = blockIdx.x;
    int tid = threadIdx.x;
    int p = tid>>2, ng = tid&3;
    float4 hi = make_float4(0.f,0.f,0.f,0.f);
    #pragma unroll
    for (int s=0; s<NSEG; ++s){
        size_t idx = (((size_t)kh*NSEG + s)*PC + p)*NC + ng*4;
        *(float4*)&hin[idx] = hi;
        float4 he = *(const float4*)&hend[idx];
        float Rseg = rc[(size_t)kh*LSEQ + s*TSEG + TSEG-1];
        hi.x = fmaf(Rseg, hi.x, he.x);
        hi.y = fmaf(Rseg, hi.y, he.y);
        hi.z = fmaf(Rseg, hi.z, he.z);
        hi.w = fmaf(Rseg, hi.w, he.w);
    }
}

// ---------------- scan phase C: fixup y += R(t) * (C_t · h_in) ----------------
__global__ __launch_bounds__(256) void k_scanC(const float* __restrict__ Ct,
                                               const float* __restrict__ rc,
                                               const float* __restrict__ hin,
                                               float* __restrict__ y){
    int seg = blockIdx.y;
    if (seg == 0) return;
    __shared__ float Hs[PC][NC+1];
    __shared__ float Cs[SCH][NC+1];
    __shared__ float Rsh[SCH];
    int kh = blockIdx.x; int k = kh/HHC, h = kh%HHC;
    int tid = threadIdx.x;
    int p = tid&63, tq = tid>>6;
    size_t hBase = ((size_t)kh*NSEG + seg)*PC*NC;
    for (int i=tid; i<PC*NC; i+=256) Hs[i>>4][i&15] = hin[hBase + i];
    __syncthreads();
    float hn[NC];
    #pragma unroll
    for (int i=0;i<NC;i++) hn[i] = Hs[p][i];

    size_t bBase = ((size_t)k*LSEQ*HHC + h)*16;
    size_t rcBase = (size_t)kh*LSEQ;
    float* ybase = y + (size_t)k*LSEQ*EC + h*64;
    int tseg0 = seg*TSEG;

    for (int c=0; c<TSEG/SCH; ++c){
        int t0 = tseg0 + c*SCH;
        for (int i=tid; i<SCH*NC; i+=256){
            int tl = i>>4, nn = i&15;
            Cs[tl][nn] = Ct[bBase + (size_t)(t0+tl)*96 + nn];
        }
        if (tid < SCH) Rsh[tid] = rc[rcBase + t0 + tid];
        __syncthreads();
        if (Rsh[0] == 0.f) break;
        #pragma unroll
        for (int jt=0; jt<SCH/4; ++jt){
            int tl = tq + jt*4;
            float R = Rsh[tl];
            if (R != 0.f){
                float corr = 0.f;
                #pragma unroll
                for (int i=0;i<NC;i++) corr = fmaf(Cs[tl][i], hn[i], corr);
                ybase[(size_t)(t0+tl)*EC + p] += R*corr;
            }
        }
        __syncthreads();
    }
}

// ---------------- g = tf32(rms(y * silu(z)) * rms_w) ----------------
__global__ void k_gate(const float* __restrict__ y, const float* __restrict__ z,
                       const float* __restrict__ rms_w, float* __restrict__ g){
    int warp = (blockIdx.x*blockDim.x + threadIdx.x) >> 5;
    int lane = threadIdx.x & 31;
    if (warp >= ROWS) return;
    size_t base = (size_t)warp*EC;
    float v[12]; float s2 = 0.f;
    #pragma unroll
    for (int j=0;j<12;j++){
        int e = lane + j*32;
        float t = y[base + e] * siluf(z[base + e]);
        v[j] = t; s2 += t*t;
    }
    #pragma unroll
    for (int off=16; off>=1; off>>=1) s2 += __shfl_xor_sync(0xffffffffu, s2, off);
    float rn = rsqrtf(s2*(1.f/384.f) + 1e-6f);
    #pragma unroll
    for (int j=0;j<12;j++){
        int e = lane + j*32;
        g[base + e] = f2tf32f(v[j]*rn*rms_w[e]);
    }
}

// ---------------- merge 4 dirs of moG -> mT (tf32) ----------------
__global__ void k_xmerge(const float* __restrict__ moG, float* __restrict__ mT){
    int idx = blockIdx.x*blockDim.x + threadIdx.x;
    if (idx >= LSEQ*EC) return;
    int l = idx / EC, e = idx % EC;
    int lt = (l%48)*48 + l/48;
    size_t r0 = (size_t)l*EC + e;
    size_t r1 = (size_t)(LSEQ + lt)*EC + e;
    size_t r2 = (size_t)(2*LSEQ + 2303 - l)*EC + e;
    size_t r3 = (size_t)(3*LSEQ + 2303 - lt)*EC + e;
    mT[idx] = f2tf32f(moG[r0] + moG[r1] + moG[r2] + moG[r3]);
}

// ---------------- LayerNorm + residual ----------------
__global__ void k_ln(const float* __restrict__ pre, const float* __restrict__ x,
                     const float* __restrict__ ln_g, const float* __restrict__ ln_b,
                     const float* __restrict__ res_scale, float* __restrict__ out){
    int warp = (blockIdx.x*blockDim.x + threadIdx.x) >> 5;
    int lane = threadIdx.x & 31;
    if (warp >= LSEQ) return;
    int l = warp;
    float v[6]; float s = 0.f;
    #pragma unroll
    for (int j=0;j<6;j++){ v[j] = pre[(size_t)l*DIMC + lane + j*32]; s += v[j]; }
    #pragma unroll
    for (int off=16; off>=1; off>>=1) s += __shfl_xor_sync(0xffffffffu, s, off);
    float mu = s*(1.f/192.f);
    float q = 0.f;
    #pragma unroll
    for (int j=0;j<6;j++){ float d = v[j]-mu; q += d*d; }
    #pragma unroll
    for (int off=16; off>=1; off>>=1) q += __shfl_xor_sync(0xffffffffu, q, off);
    float inv = rsqrtf(q*(1.f/192.f) + 1e-5f);
    float rs = res_scale[0];
    #pragma unroll
    for (int j=0;j<6;j++){
        int d = lane + j*32;
        out[(size_t)d*LSEQ + l] = x[(size_t)d*LSEQ + l]
            + rs*((v[j]-mu)*inv*ln_g[d] + ln_b[d]);
    }
}

// ---------------- launch ----------------
extern "C" void kernel_launch(void* const* d_in, const int* in_sizes, int n_in,
                              void* d_out, int out_size){
    (void)in_sizes; (void)n_in; (void)out_size;
    const float* x        = (const float*)d_in[0];
    const float* w_in     = (const float*)d_in[1];
    const float* w_zx     = (const float*)d_in[2];
    const float* w_bc     = (const float*)d_in[3];
    const float* bias_bc  = (const float*)d_in[4];
    const float* w_dt     = (const float*)d_in[5];
    const float* dt_bias  = (const float*)d_in[6];
    const float* A_log    = (const float*)d_in[7];
    const float* theta    = (const float*)d_in[8];
    const float* D_skip   = (const float*)d_in[9];
    const float* rms_w    = (const float*)d_in[10];
    const float* w_mout   = (const float*)d_in[11];
    const float* w_out    = (const float*)d_in[12];
    const float* ln_g     = (const float*)d_in[13];
    const float* ln_b     = (const float*)d_in[14];
    const float* resscale = (const float*)d_in[15];
    float* out = (float*)d_out;

    float *b_xseq,*b_projc,*b_gsil,*b_xssmt,*b_wcomb,*b_winT,*b_wmoutT,*b_woutT;
    float *b_z,*b_xh,*b_bcb,*b_dtr,*b_dtb,*b_rb,*b_cum,*b_Bt,*b_Ct,*b_y,*b_g,*b_moG,*b_mT,*b_pre;
    float *b_rc,*b_hend,*b_hin;
    cudaGetSymbolAddress((void**)&b_xseq,  g_xseq);
    cudaGetSymbolAddress((void**)&b_projc, g_projc);
    cudaGetSymbolAddress((void**)&b_gsil,  g_gsil);
    cudaGetSymbolAddress((void**)&b_xssmt, g_xssmt);
    cudaGetSymbolAddress((void**)&b_wcomb, g_wcomb);
    cudaGetSymbolAddress((void**)&b_winT,  g_winT);
    cudaGetSymbolAddress((void**)&b_wmoutT,g_wmoutT);
    cudaGetSymbolAddress((void**)&b_woutT, g_woutT);
    cudaGetSymbolAddress((void**)&b_z,     g_z);
    cudaGetSymbolAddress((void**)&b_xh,    g_xh);
    cudaGetSymbolAddress((void**)&b_bcb,   g_bcb);
    cudaGetSymbolAddress((void**)&b_dtr,   g_dtr);
    cudaGetSymbolAddress((void**)&b_dtb,   g_dtb);
    cudaGetSymbolAddress((void**)&b_rb,    g_rb);
    cudaGetSymbolAddress((void**)&b_cum,   g_cum);
    cudaGetSymbolAddress((void**)&b_Bt,    g_Bt);
    cudaGetSymbolAddress((void**)&b_Ct,    g_Ct);
    cudaGetSymbolAddress((void**)&b_y,     g_y);
    cudaGetSymbolAddress((void**)&b_g,     g_g);
    cudaGetSymbolAddress((void**)&b_moG,   g_moG);
    cudaGetSymbolAddress((void**)&b_mT,    g_mT);
    cudaGetSymbolAddress((void**)&b_pre,   g_pre);
    cudaGetSymbolAddress((void**)&b_rc,    g_rc);
    cudaGetSymbolAddress((void**)&b_hend,  g_hend);
    cudaGetSymbolAddress((void**)&b_hin,   g_hin);

    cudaFuncSetAttribute(k_gemm<0>, cudaFuncAttributeMaxDynamicSharedMemorySize, GEMM_SMEM);
    cudaFuncSetAttribute(k_gemm<1>, cudaFuncAttributeMaxDynamicSharedMemorySize, GEMM_SMEM);
    cudaFuncSetAttribute(k_gemm<2>, cudaFuncAttributeMaxDynamicSharedMemorySize, GEMM_SMEM);
    cudaFuncSetAttribute(k_gemm<3>, cudaFuncAttributeMaxDynamicSharedMemorySize, GEMM_SMEM);

    // fork the side stream FIRST (capture requires the fork edge before side-stream work)
    cudaEventRecord(g_si.evF0, 0);
    cudaStreamWaitEvent(g_si.s, g_si.evF0, 0);
    // side stream: remaining weight prep (not needed until gemm2/3/0)
    k_prepB<<<(WB3+255)/256, 256, 0, g_si.s>>>(w_mout, w_out, w_zx, w_bc,
                                               b_wmoutT, b_woutT, b_wcomb);
    cudaEventRecord(g_si.evP, g_si.s);
    // main: build + winT, then proj GEMM
    k_prepA<<<PREP_BUILD_BLKS + PREPA_W_BLKS, 256>>>(x, b_xseq, w_in, b_winT);
    k_gemm<1><<<dim3(768/128, ROWS/128), 256, GEMM_SMEM>>>(b_xseq, b_winT, b_projc,
                                                           ROWS, 768, DIMC, DIMC,
                                                           b_xssmt, b_gsil, nullptr);
    // fork: dt path on side stream, concurrent with zx GEMM
    cudaEventRecord(g_si.evF, 0);
    cudaStreamWaitEvent(g_si.s, g_si.evF, 0);
    k_dtgemv<<<ROWS/8, 256, 0, g_si.s>>>(b_projc, w_dt, b_dtr);
    k_dtscan<<<KC*HHC, 256, 0, g_si.s>>>(b_dtr, dt_bias, A_log, b_dtb, b_rb, b_cum);
    cudaEventRecord(g_si.evJ, g_si.s);
    // main: zx GEMM (needs wcomb from prepB)
    cudaStreamWaitEvent(0, g_si.evP, 0);
    k_gemm<2><<<dim3((ZXW+127)/128, ROWS/128), 256, GEMM_SMEM>>>(b_xssmt, b_wcomb, nullptr,
                                                                 ROWS, ZXW, EC, EC,
                                                                 b_z, b_xh, b_bcb);
    // join dt path before rot
    cudaStreamWaitEvent(0, g_si.evJ, 0);
    k_rot<<<ROWS/8, 256>>>(b_bcb, bias_bc, theta, b_cum, b_Bt, b_Ct);
    // split-sequence scan
    k_scanA<<<dim3(KC*HHC, NSEG), 256>>>(b_Bt, b_Ct, b_xh, b_dtb, b_rb, D_skip, b_y, b_rc, b_hend);
    k_scanB<<<KC*HHC, 256>>>(b_hend, b_rc, b_hin);
    k_scanC<<<dim3(KC*HHC, NSEG), 256>>>(b_Ct, b_rc, b_hin, b_y);
    // gated rms norm
    k_gate<<<(ROWS*32+255)/256, 256>>>(b_y, b_z, rms_w, b_g);
    // mout GEMM, epilogue * gsil
    k_gemm<3><<<dim3(EC/128, ROWS/128), 256, GEMM_SMEM>>>(b_g, b_wmoutT, b_moG,
                                                          ROWS, EC, EC, EC,
                                                          b_gsil, nullptr, nullptr);
    // 4-direction merge
    k_xmerge<<<(LSEQ*EC+255)/256, 256>>>(b_moG, b_mT);
    // output projection GEMM
    k_gemm<0><<<dim3((DIMC+127)/128, LSEQ/128), 256, GEMM_SMEM>>>(b_mT, b_woutT, b_pre,
                                                                  LSEQ, DIMC, EC, EC,
                                                                  nullptr, nullptr, nullptr);
    // layernorm + residual
    k_ln<<<(LSEQ*32+255)/256, 256>>>(b_pre, x, ln_g, ln_b, resscale, out);
}